// round 3
// baseline (speedup 1.0000x reference)
#include <cuda_runtime.h>
#include <cstddef>
#include <math.h>

#define HWSZ 16384
#define IMG 128
#define CB 128
#define C3 384
#define BATCH 8
#define HEADS 8

typedef unsigned long long u64;

// ---------------- scratch (static device globals; no allocs) ----------------
__device__ float g_xq[(size_t)BATCH * C3 * HWSZ];      // [b][384][HW]
__device__ float g_D[(size_t)BATCH * 3 * C3 * HWSZ];   // [b][scale][384][HW]
__device__ float g_q[(size_t)BATCH * CB * HWSZ];       // [b][128][HW]
__device__ float g_k[(size_t)BATCH * CB * HWSZ];
__device__ float g_gram[BATCH * HEADS * 16 * 16];
__device__ float g_ssq[BATCH * HEADS * 16];
__device__ float g_ssk[BATCH * HEADS * 16];
__device__ float g_attn[BATCH * HEADS * 16 * 16];
__device__ float g_T1[BATCH * CB * C3];
__device__ float g_M[BATCH * CB * C3];

// ---------------- packed fp32x2 helpers (Blackwell f32x2 pipe) --------------
__device__ __forceinline__ u64 pack2(float x) {
    u64 r;
    asm("mov.b64 %0, {%1, %1};" : "=l"(r) : "f"(x));
    return r;
}
__device__ __forceinline__ void fma2(u64& d, u64 a, u64 b) {
    asm("fma.rn.f32x2 %0, %1, %2, %0;" : "+l"(d) : "l"(a), "l"(b));
}

// ---------------- generic SGEMM: C[b,m,n] = sum_r A[m,r] * Brow(r)[n] -------
// B row r of batch z lives at: Bb + z*bStrB + (r>>7)*sStr + (r&127)*HWSZ
// A (weights) at A + z*aStrB, row-major [M,K].
// Double-buffered smem; A pre-packed (duplicated f32x2) at staging time.
__global__ void __launch_bounds__(256)
sgemm_kernel(const float* __restrict__ A, const float* __restrict__ Bb,
             float* __restrict__ Cb, int M, int K,
             size_t aStrB, size_t bStrB, size_t sStr, size_t cStrB) {
    __shared__ u64 As[2][8][128];     // [buf][k][m]  (16 KB)
    __shared__ float Bs[2][8][136];   // [buf][k][n]  padded to 16B mult (8.5 KB)

    const int tid = threadIdx.x;
    const int n0 = blockIdx.x * 128;
    const int m0 = blockIdx.y * 128;
    const int b = blockIdx.z;

    const float* Ab = A + (size_t)b * aStrB;
    const float* Bbase = Bb + (size_t)b * bStrB;
    float* C = Cb + (size_t)b * cStrB;

    const int tx = tid & 15;        // n sub-tile (8 wide)
    const int ty = tid >> 4;        // m sub-tile (8 tall)

    const int aRow = tid >> 1;          // 0..127
    const int aCol = (tid & 1) * 4;     // 0 or 4
    const int bRow = tid >> 5;          // 0..7
    const int bCol = (tid & 31) * 4;    // 0..124

    u64 acc[8][4];
#pragma unroll
    for (int i = 0; i < 8; i++)
#pragma unroll
        for (int j = 0; j < 4; j++) acc[i][j] = 0ull;

    // ---- stage tile 0 ----
    {
        float4 av = *(const float4*)(Ab + (size_t)(m0 + aRow) * K + aCol);
        const float* brow = Bbase + (size_t)bRow * HWSZ;  // r = bRow < 8
        float4 bv = *(const float4*)(brow + n0 + bCol);
        As[0][aCol + 0][aRow] = pack2(av.x);
        As[0][aCol + 1][aRow] = pack2(av.y);
        As[0][aCol + 2][aRow] = pack2(av.z);
        As[0][aCol + 3][aRow] = pack2(av.w);
        *(float4*)&Bs[0][bRow][bCol] = bv;
    }
    __syncthreads();

    int buf = 0;
#pragma unroll 1
    for (int k0 = 0; k0 < K; k0 += 8) {
        const bool more = (k0 + 8) < K;
        float4 av, bv;
        if (more) {
            av = *(const float4*)(Ab + (size_t)(m0 + aRow) * K + (k0 + 8) + aCol);
            int r = k0 + 8 + bRow;
            const float* brow =
                Bbase + (size_t)(r >> 7) * sStr + (size_t)(r & 127) * HWSZ;
            bv = *(const float4*)(brow + n0 + bCol);
        }

#pragma unroll
        for (int kk = 0; kk < 8; kk++) {
            const ulonglong2* apq = (const ulonglong2*)&As[buf][kk][ty * 8];
            ulonglong2 A0 = apq[0], A1 = apq[1], A2 = apq[2], A3 = apq[3];
            const ulonglong2* bpq = (const ulonglong2*)&Bs[buf][kk][tx * 8];
            ulonglong2 B0 = bpq[0], B1 = bpq[1];
            u64 a[8] = {A0.x, A0.y, A1.x, A1.y, A2.x, A2.y, A3.x, A3.y};
#pragma unroll
            for (int i = 0; i < 8; i++) {
                fma2(acc[i][0], a[i], B0.x);
                fma2(acc[i][1], a[i], B0.y);
                fma2(acc[i][2], a[i], B1.x);
                fma2(acc[i][3], a[i], B1.y);
            }
        }

        if (more) {
            int nb = buf ^ 1;
            As[nb][aCol + 0][aRow] = pack2(av.x);
            As[nb][aCol + 1][aRow] = pack2(av.y);
            As[nb][aCol + 2][aRow] = pack2(av.z);
            As[nb][aCol + 3][aRow] = pack2(av.w);
            *(float4*)&Bs[nb][bRow][bCol] = bv;
            __syncthreads();
            buf = nb;
        }
    }

#pragma unroll
    for (int i = 0; i < 8; i++) {
        float* cr = C + (size_t)(m0 + ty * 8 + i) * HWSZ + n0 + tx * 8;
        u64* cp = (u64*)cr;
#pragma unroll
        for (int j = 0; j < 4; j++) cp[j] = acc[i][j];
    }
}

// ---------------- fused multi-scale depthwise conv (3/5/7 in one pass) ------
__global__ void __launch_bounds__(256)
dwconv_kernel(const float* __restrict__ xq, const float* __restrict__ w3,
              const float* __restrict__ w5, const float* __restrict__ w7,
              float* __restrict__ D) {
    __shared__ float tile[22][72];
    __shared__ float s3[9], s5[25], s7[49];

    const int bc = blockIdx.z;           // b*384 + c
    const int b = bc / C3;
    const int c = bc % C3;
    const int x0 = blockIdx.x * 64;
    const int y0 = blockIdx.y * 16;
    const int tid = threadIdx.x;

    const float* src = xq + (size_t)bc * HWSZ;
    if (tid < 9) s3[tid] = w3[c * 9 + tid];
    if (tid < 25) s5[tid] = w5[c * 25 + tid];
    if (tid < 49) s7[tid] = w7[c * 49 + tid];

    for (int e = tid; e < 22 * 70; e += 256) {
        int iy = e / 70, ix = e % 70;
        int gy = y0 - 3 + iy, gx = x0 - 3 + ix;
        float v = 0.f;
        if (gy >= 0 && gy < IMG && gx >= 0 && gx < IMG)
            v = src[gy * IMG + gx];
        tile[iy][ix] = v;
    }
    __syncthreads();

    const int ty = tid >> 4;           // 0..15 rows
    const int tx = (tid & 15) * 4;     // 4-wide strip

    float a3[4] = {0, 0, 0, 0}, a5[4] = {0, 0, 0, 0}, a7[4] = {0, 0, 0, 0};
#pragma unroll
    for (int ky = 0; ky < 7; ky++) {
        float r[10];
#pragma unroll
        for (int j = 0; j < 10; j++) r[j] = tile[ty + ky][tx + j];
#pragma unroll
        for (int kx = 0; kx < 7; kx++) {
            float w = s7[ky * 7 + kx];
#pragma unroll
            for (int xi = 0; xi < 4; xi++) a7[xi] += r[kx + xi] * w;
        }
        if (ky >= 1 && ky <= 5) {
#pragma unroll
            for (int kx = 0; kx < 5; kx++) {
                float w = s5[(ky - 1) * 5 + kx];
#pragma unroll
                for (int xi = 0; xi < 4; xi++) a5[xi] += r[kx + 1 + xi] * w;
            }
        }
        if (ky >= 2 && ky <= 4) {
#pragma unroll
            for (int kx = 0; kx < 3; kx++) {
                float w = s3[(ky - 2) * 3 + kx];
#pragma unroll
                for (int xi = 0; xi < 4; xi++) a3[xi] += r[kx + 2 + xi] * w;
            }
        }
    }

    size_t obase = ((size_t)b * 3 * C3 + c) * HWSZ + (size_t)(y0 + ty) * IMG + (x0 + tx);
    *(float4*)&D[obase] = make_float4(a3[0], a3[1], a3[2], a3[3]);
    *(float4*)&D[obase + (size_t)C3 * HWSZ] = make_float4(a5[0], a5[1], a5[2], a5[3]);
    *(float4*)&D[obase + (size_t)2 * C3 * HWSZ] = make_float4(a7[0], a7[1], a7[2], a7[3]);
}

// ---------------- per-head Gram (q k^T) + sum-of-squares ----------------
__global__ void __launch_bounds__(256)
gram_kernel(const float* __restrict__ q, const float* __restrict__ k,
            float* __restrict__ G, float* __restrict__ SQ,
            float* __restrict__ SK) {
    __shared__ float qs[16][132];
    __shared__ float ks[16][132];
    __shared__ float Gs[16][16];
    __shared__ float Qss[16], Kss[16];

    const int tid = threadIdx.x;
    const int bh = blockIdx.y;             // b*8 + h
    const int nbase0 = blockIdx.x * 1024;  // 16-way n split

    const float* qh = q + (size_t)(bh * 16) * HWSZ;
    const float* kh = k + (size_t)(bh * 16) * HWSZ;

    Gs[tid >> 4][tid & 15] = 0.f;
    if (tid < 16) { Qss[tid] = 0.f; Kss[tid] = 0.f; }

    const int cg = tid & 3;
    const int dg = (tid >> 2) & 3;
    const int ns = tid >> 4;   // 0..15

    float acc[4][4];
#pragma unroll
    for (int i = 0; i < 4; i++)
#pragma unroll
        for (int j = 0; j < 4; j++) acc[i][j] = 0.f;
    float sq[4] = {0, 0, 0, 0}, sk[4] = {0, 0, 0, 0};

    for (int t = 0; t < 8; t++) {
        int nb = nbase0 + t * 128;
        __syncthreads();
        for (int e = tid; e < 16 * 32; e += 256) {
            int row = e >> 5, col = (e & 31) << 2;
            *(float4*)&qs[row][col] = *(const float4*)&qh[(size_t)row * HWSZ + nb + col];
            *(float4*)&ks[row][col] = *(const float4*)&kh[(size_t)row * HWSZ + nb + col];
        }
        __syncthreads();
#pragma unroll
        for (int nn = 0; nn < 8; nn++) {
            int n = ns * 8 + nn;
            float qv[4], kv[4];
#pragma unroll
            for (int i = 0; i < 4; i++) {
                qv[i] = qs[cg * 4 + i][n];
                kv[i] = ks[dg * 4 + i][n];
            }
#pragma unroll
            for (int i = 0; i < 4; i++)
#pragma unroll
                for (int j = 0; j < 4; j++) acc[i][j] += qv[i] * kv[j];
            if (dg == 0)
#pragma unroll
                for (int i = 0; i < 4; i++) sq[i] += qv[i] * qv[i];
            if (cg == 0)
#pragma unroll
                for (int i = 0; i < 4; i++) sk[i] += kv[i] * kv[i];
        }
    }
    __syncthreads();
#pragma unroll
    for (int i = 0; i < 4; i++)
#pragma unroll
        for (int j = 0; j < 4; j++)
            atomicAdd(&Gs[cg * 4 + i][dg * 4 + j], acc[i][j]);
    if (dg == 0)
#pragma unroll
        for (int i = 0; i < 4; i++) atomicAdd(&Qss[cg * 4 + i], sq[i]);
    if (cg == 0)
#pragma unroll
        for (int i = 0; i < 4; i++) atomicAdd(&Kss[dg * 4 + i], sk[i]);
    __syncthreads();

    atomicAdd(&G[(size_t)bh * 256 + tid], Gs[tid >> 4][tid & 15]);
    if (tid < 16) atomicAdd(&SQ[bh * 16 + tid], Qss[tid]);
    else if (tid < 32) atomicAdd(&SK[bh * 16 + tid - 16], Kss[tid - 16]);
}

// ---------------- normalize + temperature + softmax → attn ----------------
__global__ void attn_finalize(const float* __restrict__ G,
                              const float* __restrict__ SQ,
                              const float* __restrict__ SK,
                              const float* __restrict__ temp,
                              float* __restrict__ attn) {
    const int bh = blockIdx.x;
    const int h = bh & 7;
    const int c = threadIdx.x;
    if (c >= 16) return;
    float nq = fmaxf(sqrtf(SQ[bh * 16 + c]), 1e-12f);
    float t = temp[h];
    float s[16];
    float mx = -1e30f;
#pragma unroll
    for (int d = 0; d < 16; d++) {
        float nk = fmaxf(sqrtf(SK[bh * 16 + d]), 1e-12f);
        s[d] = G[bh * 256 + c * 16 + d] / (nq * nk) * t;
        mx = fmaxf(mx, s[d]);
    }
    float sum = 0.f;
#pragma unroll
    for (int d = 0; d < 16; d++) { s[d] = expf(s[d] - mx); sum += s[d]; }
    float inv = 1.f / sum;
#pragma unroll
    for (int d = 0; d < 16; d++) attn[bh * 256 + c * 16 + d] = s[d] * inv;
}

// ---------------- T1[b,m,r] = sum_d attn[b,h(m),m%16,d] * w_v[h*16+d, r] ----
__global__ void t1_kernel(const float* __restrict__ attn,
                          const float* __restrict__ wv,
                          float* __restrict__ T1) {
    const int bm = blockIdx.x;
    const int b = bm >> 7, m = bm & 127;
    const int h = m >> 4, cm = m & 15;
    __shared__ float a[16];
    if (threadIdx.x < 16)
        a[threadIdx.x] = attn[((b * 8 + h) * 16 + cm) * 16 + threadIdx.x];
    __syncthreads();
    const int r = threadIdx.x;  // 0..383
    float acc = 0.f;
#pragma unroll
    for (int d = 0; d < 16; d++) acc += a[d] * wv[(h * 16 + d) * C3 + r];
    T1[((size_t)b * CB + m) * C3 + r] = acc;
}

// ---------------- M[b,o,r] = sum_m w_out[o,m] * T1[b,m,r] ----------------
__global__ void m_kernel(const float* __restrict__ wout,
                         const float* __restrict__ T1,
                         float* __restrict__ Mo) {
    const int bo = blockIdx.x;
    const int b = bo >> 7, o = bo & 127;
    __shared__ float w[128];
    if (threadIdx.x < 128) w[threadIdx.x] = wout[o * 128 + threadIdx.x];
    __syncthreads();
    const int r = threadIdx.x;  // 0..383
    float acc = 0.f;
#pragma unroll 8
    for (int m = 0; m < 128; m++) acc += w[m] * T1[((size_t)b * CB + m) * C3 + r];
    Mo[((size_t)b * CB + o) * C3 + r] = acc;
}

// ---------------- zero the accumulators ----------------
__global__ void zero_stats(float* __restrict__ G, float* __restrict__ SQ,
                           float* __restrict__ SK) {
    int i = blockIdx.x * 256 + threadIdx.x;
    if (i < BATCH * HEADS * 256) G[i] = 0.f;
    if (i < BATCH * HEADS * 16) { SQ[i] = 0.f; SK[i] = 0.f; }
}

// ---------------- host launcher ----------------
extern "C" void kernel_launch(void* const* d_in, const int* in_sizes, int n_in,
                              void* d_out, int out_size) {
    const float* x     = (const float*)d_in[0];
    const float* w_qkv = (const float*)d_in[1];
    const float* w_dw3 = (const float*)d_in[2];
    const float* w_dw5 = (const float*)d_in[3];
    const float* w_dw7 = (const float*)d_in[4];
    const float* w_q   = (const float*)d_in[5];
    const float* w_k   = (const float*)d_in[6];
    const float* w_v   = (const float*)d_in[7];
    const float* w_out = (const float*)d_in[8];
    const float* temp  = (const float*)d_in[9];
    float* out = (float*)d_out;

    float *p_xq, *p_D, *p_q, *p_k, *p_gram, *p_ssq, *p_ssk, *p_attn, *p_T1, *p_M;
    cudaGetSymbolAddress((void**)&p_xq, g_xq);
    cudaGetSymbolAddress((void**)&p_D, g_D);
    cudaGetSymbolAddress((void**)&p_q, g_q);
    cudaGetSymbolAddress((void**)&p_k, g_k);
    cudaGetSymbolAddress((void**)&p_gram, g_gram);
    cudaGetSymbolAddress((void**)&p_ssq, g_ssq);
    cudaGetSymbolAddress((void**)&p_ssk, g_ssk);
    cudaGetSymbolAddress((void**)&p_attn, g_attn);
    cudaGetSymbolAddress((void**)&p_T1, g_T1);
    cudaGetSymbolAddress((void**)&p_M, g_M);

    // 0) zero gram accumulators
    zero_stats<<<64, 256>>>(p_gram, p_ssq, p_ssk);

    // 1) xq = w_qkv @ x   (M=384, K=128)
    sgemm_kernel<<<dim3(128, 3, BATCH), 256>>>(
        w_qkv, x, p_xq, 384, 128,
        (size_t)0, (size_t)128 * HWSZ, (size_t)128 * HWSZ, (size_t)C3 * HWSZ);

    // 2) fused multi-scale depthwise conv → D[b][scale][384][HW]
    dwconv_kernel<<<dim3(2, 8, BATCH * C3), 256>>>(p_xq, w_dw3, w_dw5, w_dw7, p_D);

    // 3) q = w_q @ D(q-part), k = w_k @ D(k-part)   (M=128, K=384)
    sgemm_kernel<<<dim3(128, 1, BATCH), 256>>>(
        w_q, p_D, p_q, 128, 384,
        (size_t)0, (size_t)3 * C3 * HWSZ, (size_t)C3 * HWSZ, (size_t)CB * HWSZ);
    sgemm_kernel<<<dim3(128, 1, BATCH), 256>>>(
        w_k, p_D + (size_t)CB * HWSZ, p_k, 128, 384,
        (size_t)0, (size_t)3 * C3 * HWSZ, (size_t)C3 * HWSZ, (size_t)CB * HWSZ);

    // 4) per-head Gram + sumsq, then softmax attn
    gram_kernel<<<dim3(16, BATCH * HEADS), 256>>>(p_q, p_k, p_gram, p_ssq, p_ssk);
    attn_finalize<<<BATCH * HEADS, 32>>>(p_gram, p_ssq, p_ssk, temp, p_attn);

    // 5) M_b = w_out @ blockdiag(attn) @ w_v
    t1_kernel<<<BATCH * CB, 384>>>(p_attn, w_v, p_T1);
    m_kernel<<<BATCH * CB, 384>>>(w_out, p_T1, p_M);

    // 6) out = M_b @ D(v-part)   (M=128, K=384) — v never materialized
    sgemm_kernel<<<dim3(128, 1, BATCH), 256>>>(
        p_M, p_D + (size_t)2 * CB * HWSZ, out, 128, 384,
        (size_t)CB * C3, (size_t)3 * C3 * HWSZ, (size_t)C3 * HWSZ, (size_t)CB * HWSZ);
}

// round 5
// speedup vs baseline: 1.8645x; 1.8645x over previous
#include <cuda_runtime.h>
#include <cuda_bf16.h>
#include <cstddef>
#include <cstdint>
#include <math.h>

#define HWSZ 16384
#define IMG 128
#define CB 128
#define C3 384
#define BATCH 8
#define HEADS 8
#define KCH 32

typedef __nv_bfloat16 bf16;

// smem layout (dynamic): A [2buf][2pl][128][40] bf16, B [2][2][32][136] bf16
#define SA_ROW 40
#define SB_ROW 136
#define SA_PLANE (128 * SA_ROW)          // 5120 elems
#define SB_PLANE (32 * SB_ROW)           // 4352 elems
#define SA_ELEMS (4 * SA_PLANE)
#define SB_ELEMS (4 * SB_PLANE)
#define DSM_BYTES ((SA_ELEMS + SB_ELEMS) * 2)

// ---------------- scratch ----------------
__device__ __align__(128) float g_xq[(size_t)BATCH * C3 * HWSZ];
__device__ __align__(128) bf16 g_xh[(size_t)BATCH * CB * HWSZ];
__device__ __align__(128) bf16 g_xl[(size_t)BATCH * CB * HWSZ];
__device__ __align__(128) bf16 g_Dh[(size_t)BATCH * 3 * C3 * HWSZ];
__device__ __align__(128) bf16 g_Dl[(size_t)BATCH * 3 * C3 * HWSZ];
__device__ __align__(128) float g_q[(size_t)BATCH * CB * HWSZ];
__device__ __align__(128) float g_k[(size_t)BATCH * CB * HWSZ];
__device__ __align__(128) bf16 g_wqkv_h[C3 * CB], g_wqkv_l[C3 * CB];
__device__ __align__(128) bf16 g_wq_h[CB * C3], g_wq_l[CB * C3];
__device__ __align__(128) bf16 g_wk_h[CB * C3], g_wk_l[CB * C3];
__device__ __align__(128) bf16 g_Mh[BATCH * CB * C3], g_Ml[BATCH * CB * C3];
__device__ float g_gram[BATCH * HEADS * 256];
__device__ float g_ssq[BATCH * HEADS * 16];
__device__ float g_ssk[BATCH * HEADS * 16];
__device__ float g_attn[BATCH * HEADS * 256];
__device__ float g_T1[BATCH * CB * C3];
__device__ float g_M[BATCH * CB * C3];

// ---------------- helpers ----------------
__device__ __forceinline__ uint32_t smem_u32(const void* p) {
    uint32_t a;
    asm("{ .reg .u64 t; cvta.to.shared.u64 t, %1; cvt.u32.u64 %0, t; }" : "=r"(a) : "l"(p));
    return a;
}
__device__ __forceinline__ void ldm_x4(uint32_t* r, uint32_t addr) {
    asm volatile("ldmatrix.sync.aligned.m8n8.x4.shared.b16 {%0,%1,%2,%3}, [%4];"
                 : "=r"(r[0]), "=r"(r[1]), "=r"(r[2]), "=r"(r[3]) : "r"(addr));
}
__device__ __forceinline__ void ldm_x2t(uint32_t* r, uint32_t addr) {
    asm volatile("ldmatrix.sync.aligned.m8n8.x2.trans.shared.b16 {%0,%1}, [%2];"
                 : "=r"(r[0]), "=r"(r[1]) : "r"(addr));
}
__device__ __forceinline__ void mma16816(float* d, const uint32_t* a, const uint32_t* b) {
    asm volatile(
        "mma.sync.aligned.m16n8k16.row.col.f32.bf16.bf16.f32 "
        "{%0,%1,%2,%3}, {%4,%5,%6,%7}, {%8,%9}, {%0,%1,%2,%3};"
        : "+f"(d[0]), "+f"(d[1]), "+f"(d[2]), "+f"(d[3])
        : "r"(a[0]), "r"(a[1]), "r"(a[2]), "r"(a[3]), "r"(b[0]), "r"(b[1]));
}

// ======= HMMA GEMM: C[b, m0:+128, n0:+128] = (Ah+Al) · (Bh+Bl) (3-term) =====
// A bf16 [M][Ktot] row-major (+ b*aStr). B bf16 row r at:
//   Bb + b*bStr + (r>>7)*sStr + (r&127)*HWSZ  (n contiguous).
// C fp32 row-stride HWSZ (+ b*cStr).
__global__ void __launch_bounds__(256, 1)
tc_gemm(const bf16* __restrict__ Ah, const bf16* __restrict__ Al, int Ktot, size_t aStr,
        const bf16* __restrict__ Bh, const bf16* __restrict__ Bl, size_t bStr, size_t sStr,
        float* __restrict__ C, size_t cStr) {
    extern __shared__ bf16 dsm[];
    bf16* sA = dsm;                 // [buf*2+plane][SA_PLANE]
    bf16* sB = dsm + SA_ELEMS;      // [buf*2+plane][SB_PLANE]

    const int tid = threadIdx.x, wid = tid >> 5, lid = tid & 31;
    const int n0 = blockIdx.x * 128, m0 = blockIdx.y * 128, b = blockIdx.z;
    const int wm = (wid >> 2) * 64, wn = (wid & 3) * 32;

    const bf16* Ahb = Ah + (size_t)b * aStr;
    const bf16* Alb = Al + (size_t)b * aStr;
    const bf16* Bhb = Bh + (size_t)b * bStr;
    const bf16* Blb = Bl + (size_t)b * bStr;
    const int nchunks = Ktot / KCH;

    float acc[4][4][4];
#pragma unroll
    for (int i = 0; i < 4; i++)
#pragma unroll
        for (int j = 0; j < 4; j++)
#pragma unroll
            for (int t = 0; t < 4; t++) acc[i][j][t] = 0.f;

    // staging indices: A: 1024 uint4 (2 planes x 128m x 4kq), B: 1024 uint4
    const int av = tid;                   // + i*256
    // ---- stage chunk 0 into buf 0 ----
#pragma unroll
    for (int i = 0; i < 4; i++) {
        int u = av + i * 256;
        int pl = u >> 9, v = u & 511;
        int m = v >> 2, kq = v & 3;
        const bf16* src = (pl ? Alb : Ahb) + (size_t)(m0 + m) * Ktot + kq * 8;
        *(uint4*)(sA + pl * SA_PLANE + m * SA_ROW + kq * 8) = *(const uint4*)src;
    }
#pragma unroll
    for (int i = 0; i < 4; i++) {
        int u = av + i * 256;
        int pl = u >> 9, v = u & 511;
        int k = v >> 4, nu = v & 15;
        const bf16* base = pl ? Blb : Bhb;
        const bf16* src = base + (size_t)(k >> 7) * sStr + (size_t)(k & 127) * HWSZ + n0 + nu * 8;
        *(uint4*)(sB + pl * SB_PLANE + k * SB_ROW + nu * 8) = *(const uint4*)src;
    }
    __syncthreads();

    int buf = 0;
#pragma unroll 1
    for (int ch = 0; ch < nchunks; ch++) {
        const bool more = (ch + 1) < nchunks;
        uint4 pa[4], pb[4];
        if (more) {
            const int k0 = (ch + 1) * KCH;
#pragma unroll
            for (int i = 0; i < 4; i++) {
                int u = av + i * 256;
                int pl = u >> 9, v = u & 511;
                int m = v >> 2, kq = v & 3;
                const bf16* src = (pl ? Alb : Ahb) + (size_t)(m0 + m) * Ktot + k0 + kq * 8;
                pa[i] = *(const uint4*)src;
            }
#pragma unroll
            for (int i = 0; i < 4; i++) {
                int u = av + i * 256;
                int pl = u >> 9, v = u & 511;
                int k = v >> 4, nu = v & 15;
                int r = k0 + k;
                const bf16* base = pl ? Blb : Bhb;
                pb[i] = *(const uint4*)(base + (size_t)(r >> 7) * sStr +
                                        (size_t)(r & 127) * HWSZ + n0 + nu * 8);
            }
        }

        // ---- compute from buf ----
        const uint32_t aBase0 = smem_u32(sA + (buf * 2 + 0) * SA_PLANE);
        const uint32_t aBase1 = smem_u32(sA + (buf * 2 + 1) * SA_PLANE);
        const uint32_t bBase0 = smem_u32(sB + (buf * 2 + 0) * SB_PLANE);
        const uint32_t bBase1 = smem_u32(sB + (buf * 2 + 1) * SB_PLANE);
#pragma unroll
        for (int k16 = 0; k16 < 2; k16++) {
            const int kk = k16 * 16;
            uint32_t aF[2][4][4], bF[2][4][2];
            const uint32_t aOff =
                ((uint32_t)((wm + (lid & 15)) * SA_ROW + kk + ((lid >> 4) << 3))) * 2;
#pragma unroll
            for (int mb = 0; mb < 4; mb++) {
                ldm_x4(aF[0][mb], aBase0 + aOff + mb * 16 * SA_ROW * 2);
                ldm_x4(aF[1][mb], aBase1 + aOff + mb * 16 * SA_ROW * 2);
            }
            const uint32_t bOff = ((uint32_t)((kk + (lid & 15)) * SB_ROW + wn)) * 2;
#pragma unroll
            for (int nb = 0; nb < 4; nb++) {
                ldm_x2t(bF[0][nb], bBase0 + bOff + nb * 16);
                ldm_x2t(bF[1][nb], bBase1 + bOff + nb * 16);
            }
#pragma unroll
            for (int mb = 0; mb < 4; mb++)
#pragma unroll
                for (int nb = 0; nb < 4; nb++) {
                    mma16816(acc[mb][nb], aF[0][mb], bF[0][nb]);
                    mma16816(acc[mb][nb], aF[0][mb], bF[1][nb]);
                    mma16816(acc[mb][nb], aF[1][mb], bF[0][nb]);
                }
        }
        __syncthreads();

        if (more) {
            const int nb2 = buf ^ 1;
#pragma unroll
            for (int i = 0; i < 4; i++) {
                int u = av + i * 256;
                int pl = u >> 9, v = u & 511;
                int m = v >> 2, kq = v & 3;
                *(uint4*)(sA + (nb2 * 2 + pl) * SA_PLANE + m * SA_ROW + kq * 8) = pa[i];
            }
#pragma unroll
            for (int i = 0; i < 4; i++) {
                int u = av + i * 256;
                int pl = u >> 9, v = u & 511;
                int k = v >> 4, nu = v & 15;
                *(uint4*)(sB + (nb2 * 2 + pl) * SB_PLANE + k * SB_ROW + nu * 8) = pb[i];
            }
            __syncthreads();
            buf = nb2;
        }
    }

    // ---- epilogue: direct vectorized stores ----
    float* Cp = C + (size_t)b * cStr;
    const int g = lid >> 2, t = lid & 3;
#pragma unroll
    for (int mb = 0; mb < 4; mb++)
#pragma unroll
        for (int nb = 0; nb < 4; nb++) {
            int m = m0 + wm + mb * 16 + g;
            int n = n0 + wn + nb * 8 + t * 2;
            *(float2*)&Cp[(size_t)m * HWSZ + n] = make_float2(acc[mb][nb][0], acc[mb][nb][1]);
            *(float2*)&Cp[(size_t)(m + 8) * HWSZ + n] = make_float2(acc[mb][nb][2], acc[mb][nb][3]);
        }
}

// ---------------- fp32 -> bf16 hi/lo split ----------------
__global__ void cvt_split(const float* __restrict__ src, bf16* __restrict__ hi,
                          bf16* __restrict__ lo, int n4) {
    int i = blockIdx.x * 256 + threadIdx.x;
    if (i >= n4) return;
    float4 v = ((const float4*)src)[i];
    float a[4] = {v.x, v.y, v.z, v.w};
    bf16 h[4], l[4];
#pragma unroll
    for (int j = 0; j < 4; j++) {
        h[j] = __float2bfloat16(a[j]);
        l[j] = __float2bfloat16(a[j] - __bfloat162float(h[j]));
    }
    ((uint2*)hi)[i] = *(uint2*)h;
    ((uint2*)lo)[i] = *(uint2*)l;
}

// ---------------- fused depthwise conv -> bf16 hi/lo planes ----------------
__device__ __forceinline__ void store_split4(bf16* hp, bf16* lp, const float* a) {
    bf16 h[4], l[4];
#pragma unroll
    for (int i = 0; i < 4; i++) {
        h[i] = __float2bfloat16(a[i]);
        l[i] = __float2bfloat16(a[i] - __bfloat162float(h[i]));
    }
    *(uint2*)hp = *(uint2*)h;
    *(uint2*)lp = *(uint2*)l;
}

__global__ void __launch_bounds__(256)
dwconv_kernel(const float* __restrict__ xq, const float* __restrict__ w3,
              const float* __restrict__ w5, const float* __restrict__ w7,
              bf16* __restrict__ Dh, bf16* __restrict__ Dl) {
    __shared__ float tile[22][72];
    __shared__ float s3[9], s5[25], s7[49];

    const int bc = blockIdx.z;
    const int b = bc / C3, c = bc % C3;
    const int x0 = blockIdx.x * 64, y0 = blockIdx.y * 16;
    const int tid = threadIdx.x;

    const float* src = xq + (size_t)bc * HWSZ;
    if (tid < 9) s3[tid] = w3[c * 9 + tid];
    if (tid < 25) s5[tid] = w5[c * 25 + tid];
    if (tid < 49) s7[tid] = w7[c * 49 + tid];

    for (int e = tid; e < 22 * 70; e += 256) {
        int iy = e / 70, ix = e % 70;
        int gy = y0 - 3 + iy, gx = x0 - 3 + ix;
        float v = 0.f;
        if (gy >= 0 && gy < IMG && gx >= 0 && gx < IMG) v = src[gy * IMG + gx];
        tile[iy][ix] = v;
    }
    __syncthreads();

    const int ty = tid >> 4, tx = (tid & 15) * 4;
    float a3[4] = {0, 0, 0, 0}, a5[4] = {0, 0, 0, 0}, a7[4] = {0, 0, 0, 0};
#pragma unroll
    for (int ky = 0; ky < 7; ky++) {
        float r[10];
#pragma unroll
        for (int j = 0; j < 10; j++) r[j] = tile[ty + ky][tx + j];
#pragma unroll
        for (int kx = 0; kx < 7; kx++) {
            float w = s7[ky * 7 + kx];
#pragma unroll
            for (int xi = 0; xi < 4; xi++) a7[xi] += r[kx + xi] * w;
        }
        if (ky >= 1 && ky <= 5) {
#pragma unroll
            for (int kx = 0; kx < 5; kx++) {
                float w = s5[(ky - 1) * 5 + kx];
#pragma unroll
                for (int xi = 0; xi < 4; xi++) a5[xi] += r[kx + 1 + xi] * w;
            }
        }
        if (ky >= 2 && ky <= 4) {
#pragma unroll
            for (int kx = 0; kx < 3; kx++) {
                float w = s3[(ky - 2) * 3 + kx];
#pragma unroll
                for (int xi = 0; xi < 4; xi++) a3[xi] += r[kx + 2 + xi] * w;
            }
        }
    }

    size_t o = ((size_t)b * 3 * C3 + c) * HWSZ + (size_t)(y0 + ty) * IMG + (x0 + tx);
    store_split4(Dh + o, Dl + o, a3);
    store_split4(Dh + o + (size_t)C3 * HWSZ, Dl + o + (size_t)C3 * HWSZ, a5);
    store_split4(Dh + o + (size_t)2 * C3 * HWSZ, Dl + o + (size_t)2 * C3 * HWSZ, a7);
}

// ---------------- per-head Gram + sumsq ----------------
__global__ void __launch_bounds__(256)
gram_kernel(const float* __restrict__ q, const float* __restrict__ k,
            float* __restrict__ G, float* __restrict__ SQ, float* __restrict__ SK) {
    __shared__ float qs[16][132];
    __shared__ float ks[16][132];
    __shared__ float Gs[16][16];
    __shared__ float Qss[16], Kss[16];

    const int tid = threadIdx.x;
    const int bh = blockIdx.y;
    const int nbase0 = blockIdx.x * 1024;

    const float* qh = q + (size_t)(bh * 16) * HWSZ;
    const float* kh = k + (size_t)(bh * 16) * HWSZ;

    Gs[tid >> 4][tid & 15] = 0.f;
    if (tid < 16) { Qss[tid] = 0.f; Kss[tid] = 0.f; }

    const int cg = tid & 3, dg = (tid >> 2) & 3, ns = tid >> 4;
    float acc[4][4];
#pragma unroll
    for (int i = 0; i < 4; i++)
#pragma unroll
        for (int j = 0; j < 4; j++) acc[i][j] = 0.f;
    float sq[4] = {0, 0, 0, 0}, sk[4] = {0, 0, 0, 0};

    for (int t = 0; t < 8; t++) {
        int nb = nbase0 + t * 128;
        __syncthreads();
        for (int e = tid; e < 16 * 32; e += 256) {
            int row = e >> 5, col = (e & 31) << 2;
            *(float4*)&qs[row][col] = *(const float4*)&qh[(size_t)row * HWSZ + nb + col];
            *(float4*)&ks[row][col] = *(const float4*)&kh[(size_t)row * HWSZ + nb + col];
        }
        __syncthreads();
#pragma unroll
        for (int nn = 0; nn < 8; nn++) {
            int n = ns * 8 + nn;
            float qv[4], kv[4];
#pragma unroll
            for (int i = 0; i < 4; i++) { qv[i] = qs[cg * 4 + i][n]; kv[i] = ks[dg * 4 + i][n]; }
#pragma unroll
            for (int i = 0; i < 4; i++)
#pragma unroll
                for (int j = 0; j < 4; j++) acc[i][j] += qv[i] * kv[j];
            if (dg == 0)
#pragma unroll
                for (int i = 0; i < 4; i++) sq[i] += qv[i] * qv[i];
            if (cg == 0)
#pragma unroll
                for (int i = 0; i < 4; i++) sk[i] += kv[i] * kv[i];
        }
    }
    __syncthreads();
#pragma unroll
    for (int i = 0; i < 4; i++)
#pragma unroll
        for (int j = 0; j < 4; j++) atomicAdd(&Gs[cg * 4 + i][dg * 4 + j], acc[i][j]);
    if (dg == 0)
#pragma unroll
        for (int i = 0; i < 4; i++) atomicAdd(&Qss[cg * 4 + i], sq[i]);
    if (cg == 0)
#pragma unroll
        for (int i = 0; i < 4; i++) atomicAdd(&Kss[dg * 4 + i], sk[i]);
    __syncthreads();

    atomicAdd(&G[(size_t)bh * 256 + tid], Gs[tid >> 4][tid & 15]);
    if (tid < 16) atomicAdd(&SQ[bh * 16 + tid], Qss[tid]);
    else if (tid < 32) atomicAdd(&SK[bh * 16 + tid - 16], Kss[tid - 16]);
}

// ---------------- softmax finalize ----------------
__global__ void attn_finalize(const float* __restrict__ G, const float* __restrict__ SQ,
                              const float* __restrict__ SK, const float* __restrict__ temp,
                              float* __restrict__ attn) {
    const int bh = blockIdx.x, h = bh & 7, c = threadIdx.x;
    if (c >= 16) return;
    float nq = fmaxf(sqrtf(SQ[bh * 16 + c]), 1e-12f);
    float t = temp[h];
    float s[16], mx = -1e30f;
#pragma unroll
    for (int d = 0; d < 16; d++) {
        float nk = fmaxf(sqrtf(SK[bh * 16 + d]), 1e-12f);
        s[d] = G[bh * 256 + c * 16 + d] / (nq * nk) * t;
        mx = fmaxf(mx, s[d]);
    }
    float sum = 0.f;
#pragma unroll
    for (int d = 0; d < 16; d++) { s[d] = expf(s[d] - mx); sum += s[d]; }
    float inv = 1.f / sum;
#pragma unroll
    for (int d = 0; d < 16; d++) attn[bh * 256 + c * 16 + d] = s[d] * inv;
}

// ---------------- T1 / M ----------------
__global__ void t1_kernel(const float* __restrict__ attn, const float* __restrict__ wv,
                          float* __restrict__ T1) {
    const int bm = blockIdx.x, b = bm >> 7, m = bm & 127, h = m >> 4, cm = m & 15;
    __shared__ float a[16];
    if (threadIdx.x < 16) a[threadIdx.x] = attn[((b * 8 + h) * 16 + cm) * 16 + threadIdx.x];
    __syncthreads();
    const int r = threadIdx.x;
    float acc = 0.f;
#pragma unroll
    for (int d = 0; d < 16; d++) acc += a[d] * wv[(h * 16 + d) * C3 + r];
    T1[((size_t)b * CB + m) * C3 + r] = acc;
}

__global__ void m_kernel(const float* __restrict__ wout, const float* __restrict__ T1,
                         float* __restrict__ Mo) {
    const int bo = blockIdx.x, b = bo >> 7, o = bo & 127;
    __shared__ float w[128];
    if (threadIdx.x < 128) w[threadIdx.x] = wout[o * 128 + threadIdx.x];
    __syncthreads();
    const int r = threadIdx.x;
    float acc = 0.f;
#pragma unroll 8
    for (int m = 0; m < 128; m++) acc += w[m] * T1[((size_t)b * CB + m) * C3 + r];
    Mo[((size_t)b * CB + o) * C3 + r] = acc;
}

__global__ void zero_stats(float* __restrict__ G, float* __restrict__ SQ,
                           float* __restrict__ SK) {
    int i = blockIdx.x * 256 + threadIdx.x;
    if (i < BATCH * HEADS * 256) G[i] = 0.f;
    if (i < BATCH * HEADS * 16) { SQ[i] = 0.f; SK[i] = 0.f; }
}

// ---------------- host launcher ----------------
extern "C" void kernel_launch(void* const* d_in, const int* in_sizes, int n_in,
                              void* d_out, int out_size) {
    const float* x     = (const float*)d_in[0];
    const float* w_qkv = (const float*)d_in[1];
    const float* w_dw3 = (const float*)d_in[2];
    const float* w_dw5 = (const float*)d_in[3];
    const float* w_dw7 = (const float*)d_in[4];
    const float* w_q   = (const float*)d_in[5];
    const float* w_k   = (const float*)d_in[6];
    const float* w_v   = (const float*)d_in[7];
    const float* w_out = (const float*)d_in[8];
    const float* temp  = (const float*)d_in[9];
    float* out = (float*)d_out;

    float *p_xq, *p_q, *p_k, *p_gram, *p_ssq, *p_ssk, *p_attn, *p_T1, *p_M;
    bf16 *p_xh, *p_xl, *p_Dh, *p_Dl, *p_wqkvh, *p_wqkvl, *p_wqh, *p_wql, *p_wkh, *p_wkl, *p_Mh, *p_Ml;
    cudaGetSymbolAddress((void**)&p_xq, g_xq);
    cudaGetSymbolAddress((void**)&p_xh, g_xh);
    cudaGetSymbolAddress((void**)&p_xl, g_xl);
    cudaGetSymbolAddress((void**)&p_Dh, g_Dh);
    cudaGetSymbolAddress((void**)&p_Dl, g_Dl);
    cudaGetSymbolAddress((void**)&p_q, g_q);
    cudaGetSymbolAddress((void**)&p_k, g_k);
    cudaGetSymbolAddress((void**)&p_gram, g_gram);
    cudaGetSymbolAddress((void**)&p_ssq, g_ssq);
    cudaGetSymbolAddress((void**)&p_ssk, g_ssk);
    cudaGetSymbolAddress((void**)&p_attn, g_attn);
    cudaGetSymbolAddress((void**)&p_T1, g_T1);
    cudaGetSymbolAddress((void**)&p_M, g_M);
    cudaGetSymbolAddress((void**)&p_wqkvh, g_wqkv_h);
    cudaGetSymbolAddress((void**)&p_wqkvl, g_wqkv_l);
    cudaGetSymbolAddress((void**)&p_wqh, g_wq_h);
    cudaGetSymbolAddress((void**)&p_wql, g_wq_l);
    cudaGetSymbolAddress((void**)&p_wkh, g_wk_h);
    cudaGetSymbolAddress((void**)&p_wkl, g_wk_l);
    cudaGetSymbolAddress((void**)&p_Mh, g_Mh);
    cudaGetSymbolAddress((void**)&p_Ml, g_Ml);

    cudaFuncSetAttribute(tc_gemm, cudaFuncAttributeMaxDynamicSharedMemorySize, DSM_BYTES);

    zero_stats<<<64, 256>>>(p_gram, p_ssq, p_ssk);

    // splits
    {
        int n4 = BATCH * CB * HWSZ / 4;
        cvt_split<<<(n4 + 255) / 256, 256>>>(x, p_xh, p_xl, n4);
    }
    cvt_split<<<48, 256>>>(w_qkv, p_wqkvh, p_wqkvl, C3 * CB / 4);
    cvt_split<<<48, 256>>>(w_q, p_wqh, p_wql, CB * C3 / 4);
    cvt_split<<<48, 256>>>(w_k, p_wkh, p_wkl, CB * C3 / 4);

    // 1) xq = w_qkv @ x  (M=384, K=128)
    tc_gemm<<<dim3(128, 3, BATCH), 256, DSM_BYTES>>>(
        p_wqkvh, p_wqkvl, 128, (size_t)0,
        p_xh, p_xl, (size_t)CB * HWSZ, (size_t)CB * HWSZ,
        p_xq, (size_t)C3 * HWSZ);

    // 2) depthwise conv -> D hi/lo
    dwconv_kernel<<<dim3(2, 8, BATCH * C3), 256>>>(p_xq, w_dw3, w_dw5, w_dw7, p_Dh, p_Dl);

    // 3) q / k projections (M=128, K=384)
    tc_gemm<<<dim3(128, 1, BATCH), 256, DSM_BYTES>>>(
        p_wqh, p_wql, 384, (size_t)0,
        p_Dh, p_Dl, (size_t)3 * C3 * HWSZ, (size_t)C3 * HWSZ,
        p_q, (size_t)CB * HWSZ);
    tc_gemm<<<dim3(128, 1, BATCH), 256, DSM_BYTES>>>(
        p_wkh, p_wkl, 384, (size_t)0,
        p_Dh + (size_t)CB * HWSZ, p_Dl + (size_t)CB * HWSZ, (size_t)3 * C3 * HWSZ, (size_t)C3 * HWSZ,
        p_k, (size_t)CB * HWSZ);

    // 4) gram + softmax
    gram_kernel<<<dim3(16, BATCH * HEADS), 256>>>(p_q, p_k, p_gram, p_ssq, p_ssk);
    attn_finalize<<<BATCH * HEADS, 32>>>(p_gram, p_ssq, p_ssk, temp, p_attn);

    // 5) M_b = w_out @ blockdiag(attn) @ w_v  -> bf16 split
    t1_kernel<<<BATCH * CB, 384>>>(p_attn, w_v, p_T1);
    m_kernel<<<BATCH * CB, 384>>>(w_out, p_T1, p_M);
    cvt_split<<<384, 256>>>(p_M, p_Mh, p_Ml, BATCH * CB * C3 / 4);

    // 6) out = M_b @ D(v-part)  (M=128, K=384)
    tc_gemm<<<dim3(128, 1, BATCH), 256, DSM_BYTES>>>(
        p_Mh, p_Ml, 384, (size_t)CB * C3,
        p_Dh + (size_t)2 * CB * HWSZ, p_Dl + (size_t)2 * CB * HWSZ, (size_t)3 * C3 * HWSZ, (size_t)C3 * HWSZ,
        out, (size_t)CB * HWSZ);
}

// round 6
// speedup vs baseline: 1.9331x; 1.0368x over previous
#include <cuda_runtime.h>
#include <cuda_bf16.h>
#include <cstddef>
#include <cstdint>
#include <math.h>

#define HWSZ 16384
#define IMG 128
#define CB 128
#define C3 384
#define BATCH 8
#define HEADS 8
#define KCH 32

typedef __nv_bfloat16 bf16;

// smem: A [2buf][2pl][128][40] bf16, B [2][2][32][136] bf16
#define SA_ROW 40
#define SB_ROW 136
#define SA_PLANE (128 * SA_ROW)
#define SB_PLANE (32 * SB_ROW)
#define SA_ELEMS (4 * SA_PLANE)
#define SB_ELEMS (4 * SB_PLANE)
#define STG_BYTES ((SA_ELEMS + SB_ELEMS) * 2)      // 75776
#define QT_BYTES (128 * 132 * 4)                   // 67584 (transposed tile)
#define QKG_BYTES (STG_BYTES + QT_BYTES)           // 143360

// ---------------- scratch ----------------
__device__ __align__(128) float g_xq[(size_t)BATCH * C3 * HWSZ];
__device__ __align__(128) bf16 g_xh[(size_t)BATCH * CB * HWSZ];
__device__ __align__(128) bf16 g_xl[(size_t)BATCH * CB * HWSZ];
__device__ __align__(128) bf16 g_Dh[(size_t)BATCH * 3 * C3 * HWSZ];
__device__ __align__(128) bf16 g_Dl[(size_t)BATCH * 3 * C3 * HWSZ];
__device__ __align__(128) bf16 g_wqkv_h[C3 * CB], g_wqkv_l[C3 * CB];
__device__ __align__(128) bf16 g_wq_h[CB * C3], g_wq_l[CB * C3];
__device__ __align__(128) bf16 g_wk_h[CB * C3], g_wk_l[CB * C3];
__device__ __align__(128) bf16 g_Mh[BATCH * CB * C3], g_Ml[BATCH * CB * C3];
__device__ float g_gram[BATCH * HEADS * 256];
__device__ float g_ssq[BATCH * HEADS * 16];
__device__ float g_ssk[BATCH * HEADS * 16];
__device__ float g_attn[BATCH * HEADS * 256];
__device__ float g_T1[BATCH * CB * C3];
__device__ float g_M[BATCH * CB * C3];

// ---------------- helpers ----------------
__device__ __forceinline__ uint32_t smem_u32(const void* p) {
    uint32_t a;
    asm("{ .reg .u64 t; cvta.to.shared.u64 t, %1; cvt.u32.u64 %0, t; }" : "=r"(a) : "l"(p));
    return a;
}
__device__ __forceinline__ void ldm_x4(uint32_t* r, uint32_t addr) {
    asm volatile("ldmatrix.sync.aligned.m8n8.x4.shared.b16 {%0,%1,%2,%3}, [%4];"
                 : "=r"(r[0]), "=r"(r[1]), "=r"(r[2]), "=r"(r[3]) : "r"(addr));
}
__device__ __forceinline__ void ldm_x2t(uint32_t* r, uint32_t addr) {
    asm volatile("ldmatrix.sync.aligned.m8n8.x2.trans.shared.b16 {%0,%1}, [%2];"
                 : "=r"(r[0]), "=r"(r[1]) : "r"(addr));
}
__device__ __forceinline__ void mma16816(float* d, const uint32_t* a, const uint32_t* b) {
    asm volatile(
        "mma.sync.aligned.m16n8k16.row.col.f32.bf16.bf16.f32 "
        "{%0,%1,%2,%3}, {%4,%5,%6,%7}, {%8,%9}, {%0,%1,%2,%3};"
        : "+f"(d[0]), "+f"(d[1]), "+f"(d[2]), "+f"(d[3])
        : "r"(a[0]), "r"(a[1]), "r"(a[2]), "r"(a[3]), "r"(b[0]), "r"(b[1]));
}

// ---- shared HMMA mainloop: acc += (Ah+Al)·(Bh+Bl), M=128, N=128 tile ----
// A row-major [128][Ktot]; B row r at: B + (r>>7)*sStr + (r&127)*HWSZ, +n0.
__device__ __forceinline__ void gemm_mainloop(
    const bf16* __restrict__ Ahb, const bf16* __restrict__ Alb, int Ktot, int m0,
    const bf16* __restrict__ Bhb, const bf16* __restrict__ Blb, size_t sStr, int n0,
    bf16* sA, bf16* sB, int tid, int wid, int lid, float acc[4][4][4]) {
    const int wm = (wid >> 2) * 64, wn = (wid & 3) * 32;
    const int nchunks = Ktot / KCH;
    const int av = tid;

    // stage chunk 0 into buf 0
#pragma unroll
    for (int i = 0; i < 4; i++) {
        int u = av + i * 256;
        int pl = u >> 9, v = u & 511;
        int m = v >> 2, kq = v & 3;
        const bf16* src = (pl ? Alb : Ahb) + (size_t)(m0 + m) * Ktot + kq * 8;
        *(uint4*)(sA + pl * SA_PLANE + m * SA_ROW + kq * 8) = *(const uint4*)src;
    }
#pragma unroll
    for (int i = 0; i < 4; i++) {
        int u = av + i * 256;
        int pl = u >> 9, v = u & 511;
        int k = v >> 4, nu = v & 15;
        const bf16* base = pl ? Blb : Bhb;
        *(uint4*)(sB + pl * SB_PLANE + k * SB_ROW + nu * 8) =
            *(const uint4*)(base + (size_t)(k >> 7) * sStr + (size_t)(k & 127) * HWSZ + n0 + nu * 8);
    }
    __syncthreads();

    int buf = 0;
#pragma unroll 1
    for (int ch = 0; ch < nchunks; ch++) {
        const bool more = (ch + 1) < nchunks;
        uint4 pa[4], pb[4];
        if (more) {
            const int k0 = (ch + 1) * KCH;
#pragma unroll
            for (int i = 0; i < 4; i++) {
                int u = av + i * 256;
                int pl = u >> 9, v = u & 511;
                int m = v >> 2, kq = v & 3;
                pa[i] = *(const uint4*)((pl ? Alb : Ahb) + (size_t)(m0 + m) * Ktot + k0 + kq * 8);
            }
#pragma unroll
            for (int i = 0; i < 4; i++) {
                int u = av + i * 256;
                int pl = u >> 9, v = u & 511;
                int k = v >> 4, nu = v & 15;
                int r = k0 + k;
                const bf16* base = pl ? Blb : Bhb;
                pb[i] = *(const uint4*)(base + (size_t)(r >> 7) * sStr +
                                        (size_t)(r & 127) * HWSZ + n0 + nu * 8);
            }
        }

        const uint32_t aBase0 = smem_u32(sA + (buf * 2 + 0) * SA_PLANE);
        const uint32_t aBase1 = smem_u32(sA + (buf * 2 + 1) * SA_PLANE);
        const uint32_t bBase0 = smem_u32(sB + (buf * 2 + 0) * SB_PLANE);
        const uint32_t bBase1 = smem_u32(sB + (buf * 2 + 1) * SB_PLANE);
#pragma unroll
        for (int k16 = 0; k16 < 2; k16++) {
            const int kk = k16 * 16;
            uint32_t aF[2][4][4], bF[2][4][2];
            const uint32_t aOff =
                ((uint32_t)((wm + (lid & 15)) * SA_ROW + kk + ((lid >> 4) << 3))) * 2;
#pragma unroll
            for (int mb = 0; mb < 4; mb++) {
                ldm_x4(aF[0][mb], aBase0 + aOff + mb * 16 * SA_ROW * 2);
                ldm_x4(aF[1][mb], aBase1 + aOff + mb * 16 * SA_ROW * 2);
            }
            const uint32_t bOff = ((uint32_t)((kk + (lid & 15)) * SB_ROW + wn)) * 2;
#pragma unroll
            for (int nb = 0; nb < 4; nb++) {
                ldm_x2t(bF[0][nb], bBase0 + bOff + nb * 16);
                ldm_x2t(bF[1][nb], bBase1 + bOff + nb * 16);
            }
#pragma unroll
            for (int mb = 0; mb < 4; mb++)
#pragma unroll
                for (int nb = 0; nb < 4; nb++) {
                    mma16816(acc[mb][nb], aF[0][mb], bF[0][nb]);
                    mma16816(acc[mb][nb], aF[0][mb], bF[1][nb]);
                    mma16816(acc[mb][nb], aF[1][mb], bF[0][nb]);
                }
        }
        __syncthreads();

        if (more) {
            const int nb2 = buf ^ 1;
#pragma unroll
            for (int i = 0; i < 4; i++) {
                int u = av + i * 256;
                int pl = u >> 9, v = u & 511;
                int m = v >> 2, kq = v & 3;
                *(uint4*)(sA + (nb2 * 2 + pl) * SA_PLANE + m * SA_ROW + kq * 8) = pa[i];
            }
#pragma unroll
            for (int i = 0; i < 4; i++) {
                int u = av + i * 256;
                int pl = u >> 9, v = u & 511;
                int k = v >> 4, nu = v & 15;
                *(uint4*)(sB + (nb2 * 2 + pl) * SB_PLANE + k * SB_ROW + nu * 8) = pb[i];
            }
            __syncthreads();
            buf = nb2;
        }
    }
}

// ================= standalone GEMM (gemm1, out-gemm) =================
// m-tiles on blockIdx.x (fastest) for L2 reuse of B across m.
__global__ void __launch_bounds__(256, 1)
tc_gemm(const bf16* __restrict__ Ah, const bf16* __restrict__ Al, int Ktot, size_t aStr,
        const bf16* __restrict__ Bh, const bf16* __restrict__ Bl, size_t bStr, size_t sStr,
        float* __restrict__ C, size_t cStr) {
    extern __shared__ bf16 dsm[];
    bf16* sA = dsm;
    bf16* sB = dsm + SA_ELEMS;

    const int tid = threadIdx.x, wid = tid >> 5, lid = tid & 31;
    const int m0 = blockIdx.x * 128, n0 = blockIdx.y * 128, b = blockIdx.z;
    const int wm = (wid >> 2) * 64, wn = (wid & 3) * 32;

    float acc[4][4][4];
#pragma unroll
    for (int i = 0; i < 4; i++)
#pragma unroll
        for (int j = 0; j < 4; j++)
#pragma unroll
            for (int t = 0; t < 4; t++) acc[i][j][t] = 0.f;

    gemm_mainloop(Ah + (size_t)b * aStr, Al + (size_t)b * aStr, Ktot, m0,
                  Bh + (size_t)b * bStr, Bl + (size_t)b * bStr, sStr, n0,
                  sA, sB, tid, wid, lid, acc);

    float* Cp = C + (size_t)b * cStr;
    const int g = lid >> 2, t = lid & 3;
#pragma unroll
    for (int mb = 0; mb < 4; mb++)
#pragma unroll
        for (int nb = 0; nb < 4; nb++) {
            int m = m0 + wm + mb * 16 + g;
            int n = n0 + wn + nb * 8 + t * 2;
            *(float2*)&Cp[(size_t)m * HWSZ + n] = make_float2(acc[mb][nb][0], acc[mb][nb][1]);
            *(float2*)&Cp[(size_t)(m + 8) * HWSZ + n] = make_float2(acc[mb][nb][2], acc[mb][nb][3]);
        }
}

// ====== fused q-proj + k-proj + per-head gram/sumsq (no q/k in DRAM) ======
__global__ void __launch_bounds__(256, 1)
qk_gram(const bf16* __restrict__ wqh, const bf16* __restrict__ wql,
        const bf16* __restrict__ wkh, const bf16* __restrict__ wkl,
        const bf16* __restrict__ Dh, const bf16* __restrict__ Dl,
        float* __restrict__ G, float* __restrict__ SQ, float* __restrict__ SK) {
    extern __shared__ bf16 dsm[];
    bf16* sA = dsm;
    bf16* sB = dsm + SA_ELEMS;
    float* qst = (float*)(dsm + SA_ELEMS + SB_ELEMS);  // [128 n][132] transposed q
    float* kst = (float*)dsm;                          // reuses staging after phase B

    const int tid = threadIdx.x, wid = tid >> 5, lid = tid & 31;
    const int n0 = blockIdx.x * 128, b = blockIdx.y;
    const int wm = (wid >> 2) * 64, wn = (wid & 3) * 32;
    const int g = lid >> 2, t4 = lid & 3;

    const bf16* Dhb = Dh + (size_t)b * 3 * C3 * HWSZ;
    const bf16* Dlb = Dl + (size_t)b * 3 * C3 * HWSZ;

    float acc[4][4][4];
#pragma unroll
    for (int i = 0; i < 4; i++)
#pragma unroll
        for (int j = 0; j < 4; j++)
#pragma unroll
            for (int t = 0; t < 4; t++) acc[i][j][t] = 0.f;

    // ---- phase A: q tile ----
    gemm_mainloop(wqh, wql, C3, 0, Dhb, Dlb, (size_t)C3 * HWSZ, n0,
                  sA, sB, tid, wid, lid, acc);
#pragma unroll
    for (int mb = 0; mb < 4; mb++)
#pragma unroll
        for (int nb = 0; nb < 4; nb++) {
            int m = wm + mb * 16 + g;
            int n = wn + nb * 8 + t4 * 2;
            qst[n * 132 + m] = acc[mb][nb][0];
            qst[(n + 1) * 132 + m] = acc[mb][nb][1];
            qst[n * 132 + m + 8] = acc[mb][nb][2];
            qst[(n + 1) * 132 + m + 8] = acc[mb][nb][3];
            acc[mb][nb][0] = acc[mb][nb][1] = acc[mb][nb][2] = acc[mb][nb][3] = 0.f;
        }
    __syncthreads();

    // ---- phase B: k tile ----
    gemm_mainloop(wkh, wkl, C3, 0, Dhb + (size_t)CB * HWSZ, Dlb + (size_t)CB * HWSZ,
                  (size_t)C3 * HWSZ, n0, sA, sB, tid, wid, lid, acc);
    __syncthreads();   // everyone done reading staging before kst overwrite
#pragma unroll
    for (int mb = 0; mb < 4; mb++)
#pragma unroll
        for (int nb = 0; nb < 4; nb++) {
            int m = wm + mb * 16 + g;
            int n = wn + nb * 8 + t4 * 2;
            kst[n * 132 + m] = acc[mb][nb][0];
            kst[(n + 1) * 132 + m] = acc[mb][nb][1];
            kst[n * 132 + m + 8] = acc[mb][nb][2];
            kst[(n + 1) * 132 + m + 8] = acc[mb][nb][3];
        }
    __syncthreads();

    // ---- phase C: per-head gram + sumsq ----
    {
        const int h = wid;                // 8 warps = 8 heads
        const int c = lid >> 1;           // 0..15
        const int d0 = (lid & 1) * 8;     // 0 or 8
        float a8[8] = {0, 0, 0, 0, 0, 0, 0, 0};
        float sq = 0.f, sk8[8] = {0, 0, 0, 0, 0, 0, 0, 0};
#pragma unroll 4
        for (int n = 0; n < 128; n++) {
            float qv = qst[n * 132 + h * 16 + c];
            float4 k0 = *(float4*)&kst[n * 132 + h * 16 + d0];
            float4 k1 = *(float4*)&kst[n * 132 + h * 16 + d0 + 4];
            a8[0] += qv * k0.x; a8[1] += qv * k0.y; a8[2] += qv * k0.z; a8[3] += qv * k0.w;
            a8[4] += qv * k1.x; a8[5] += qv * k1.y; a8[6] += qv * k1.z; a8[7] += qv * k1.w;
            if ((lid & 1) == 0) sq += qv * qv;
            if (c == 0) {
                sk8[0] += k0.x * k0.x; sk8[1] += k0.y * k0.y;
                sk8[2] += k0.z * k0.z; sk8[3] += k0.w * k0.w;
                sk8[4] += k1.x * k1.x; sk8[5] += k1.y * k1.y;
                sk8[6] += k1.z * k1.z; sk8[7] += k1.w * k1.w;
            }
        }
        const int bh = b * HEADS + h;
#pragma unroll
        for (int j = 0; j < 8; j++)
            atomicAdd(&G[(size_t)bh * 256 + c * 16 + d0 + j], a8[j]);
        if ((lid & 1) == 0) atomicAdd(&SQ[bh * 16 + c], sq);
        if (c == 0)
#pragma unroll
            for (int j = 0; j < 8; j++) atomicAdd(&SK[bh * 16 + d0 + j], sk8[j]);
    }
}

// ---------------- fp32 -> bf16 hi/lo split ----------------
__global__ void cvt_split(const float* __restrict__ src, bf16* __restrict__ hi,
                          bf16* __restrict__ lo, int n4) {
    int i = blockIdx.x * 256 + threadIdx.x;
    if (i >= n4) return;
    float4 v = ((const float4*)src)[i];
    float a[4] = {v.x, v.y, v.z, v.w};
    bf16 h[4], l[4];
#pragma unroll
    for (int j = 0; j < 4; j++) {
        h[j] = __float2bfloat16(a[j]);
        l[j] = __float2bfloat16(a[j] - __bfloat162float(h[j]));
    }
    ((uint2*)hi)[i] = *(uint2*)h;
    ((uint2*)lo)[i] = *(uint2*)l;
}

// ---------------- fused depthwise conv -> bf16 hi/lo planes ----------------
__device__ __forceinline__ void store_split4(bf16* hp, bf16* lp, const float* a) {
    bf16 h[4], l[4];
#pragma unroll
    for (int i = 0; i < 4; i++) {
        h[i] = __float2bfloat16(a[i]);
        l[i] = __float2bfloat16(a[i] - __bfloat162float(h[i]));
    }
    *(uint2*)hp = *(uint2*)h;
    *(uint2*)lp = *(uint2*)l;
}

__global__ void __launch_bounds__(256)
dwconv_kernel(const float* __restrict__ xq, const float* __restrict__ w3,
              const float* __restrict__ w5, const float* __restrict__ w7,
              bf16* __restrict__ Dh, bf16* __restrict__ Dl) {
    __shared__ float tile[22][72];
    __shared__ float s3[9], s5[25], s7[49];

    const int bc = blockIdx.z;
    const int b = bc / C3, c = bc % C3;
    const int x0 = blockIdx.x * 64, y0 = blockIdx.y * 16;
    const int tid = threadIdx.x;

    const float* src = xq + (size_t)bc * HWSZ;
    if (tid < 9) s3[tid] = w3[c * 9 + tid];
    if (tid < 25) s5[tid] = w5[c * 25 + tid];
    if (tid < 49) s7[tid] = w7[c * 49 + tid];

    for (int e = tid; e < 22 * 70; e += 256) {
        int iy = e / 70, ix = e % 70;
        int gy = y0 - 3 + iy, gx = x0 - 3 + ix;
        float v = 0.f;
        if (gy >= 0 && gy < IMG && gx >= 0 && gx < IMG) v = src[gy * IMG + gx];
        tile[iy][ix] = v;
    }
    __syncthreads();

    const int ty = tid >> 4, tx = (tid & 15) * 4;
    float a3[4] = {0, 0, 0, 0}, a5[4] = {0, 0, 0, 0}, a7[4] = {0, 0, 0, 0};
#pragma unroll
    for (int ky = 0; ky < 7; ky++) {
        float r[10];
#pragma unroll
        for (int j = 0; j < 10; j++) r[j] = tile[ty + ky][tx + j];
#pragma unroll
        for (int kx = 0; kx < 7; kx++) {
            float w = s7[ky * 7 + kx];
#pragma unroll
            for (int xi = 0; xi < 4; xi++) a7[xi] += r[kx + xi] * w;
        }
        if (ky >= 1 && ky <= 5) {
#pragma unroll
            for (int kx = 0; kx < 5; kx++) {
                float w = s5[(ky - 1) * 5 + kx];
#pragma unroll
                for (int xi = 0; xi < 4; xi++) a5[xi] += r[kx + 1 + xi] * w;
            }
        }
        if (ky >= 2 && ky <= 4) {
#pragma unroll
            for (int kx = 0; kx < 3; kx++) {
                float w = s3[(ky - 2) * 3 + kx];
#pragma unroll
                for (int xi = 0; xi < 4; xi++) a3[xi] += r[kx + 2 + xi] * w;
            }
        }
    }

    size_t o = ((size_t)b * 3 * C3 + c) * HWSZ + (size_t)(y0 + ty) * IMG + (x0 + tx);
    store_split4(Dh + o, Dl + o, a3);
    store_split4(Dh + o + (size_t)C3 * HWSZ, Dl + o + (size_t)C3 * HWSZ, a5);
    store_split4(Dh + o + (size_t)2 * C3 * HWSZ, Dl + o + (size_t)2 * C3 * HWSZ, a7);
}

// ---------------- softmax finalize ----------------
__global__ void attn_finalize(const float* __restrict__ G, const float* __restrict__ SQ,
                              const float* __restrict__ SK, const float* __restrict__ temp,
                              float* __restrict__ attn) {
    const int bh = blockIdx.x, h = bh & 7, c = threadIdx.x;
    if (c >= 16) return;
    float nq = fmaxf(sqrtf(SQ[bh * 16 + c]), 1e-12f);
    float t = temp[h];
    float s[16], mx = -1e30f;
#pragma unroll
    for (int d = 0; d < 16; d++) {
        float nk = fmaxf(sqrtf(SK[bh * 16 + d]), 1e-12f);
        s[d] = G[bh * 256 + c * 16 + d] / (nq * nk) * t;
        mx = fmaxf(mx, s[d]);
    }
    float sum = 0.f;
#pragma unroll
    for (int d = 0; d < 16; d++) { s[d] = expf(s[d] - mx); sum += s[d]; }
    float inv = 1.f / sum;
#pragma unroll
    for (int d = 0; d < 16; d++) attn[bh * 256 + c * 16 + d] = s[d] * inv;
}

// ---------------- T1 / M ----------------
__global__ void t1_kernel(const float* __restrict__ attn, const float* __restrict__ wv,
                          float* __restrict__ T1) {
    const int bm = blockIdx.x, b = bm >> 7, m = bm & 127, h = m >> 4, cm = m & 15;
    __shared__ float a[16];
    if (threadIdx.x < 16) a[threadIdx.x] = attn[((b * 8 + h) * 16 + cm) * 16 + threadIdx.x];
    __syncthreads();
    const int r = threadIdx.x;
    float acc = 0.f;
#pragma unroll
    for (int d = 0; d < 16; d++) acc += a[d] * wv[(h * 16 + d) * C3 + r];
    T1[((size_t)b * CB + m) * C3 + r] = acc;
}

__global__ void m_kernel(const float* __restrict__ wout, const float* __restrict__ T1,
                         float* __restrict__ Mo) {
    const int bo = blockIdx.x, b = bo >> 7, o = bo & 127;
    __shared__ float w[128];
    if (threadIdx.x < 128) w[threadIdx.x] = wout[o * 128 + threadIdx.x];
    __syncthreads();
    const int r = threadIdx.x;
    float acc = 0.f;
#pragma unroll 8
    for (int m = 0; m < 128; m++) acc += w[m] * T1[((size_t)b * CB + m) * C3 + r];
    Mo[((size_t)b * CB + o) * C3 + r] = acc;
}

__global__ void zero_stats(float* __restrict__ G, float* __restrict__ SQ,
                           float* __restrict__ SK) {
    int i = blockIdx.x * 256 + threadIdx.x;
    if (i < BATCH * HEADS * 256) G[i] = 0.f;
    if (i < BATCH * HEADS * 16) { SQ[i] = 0.f; SK[i] = 0.f; }
}

// ---------------- host launcher ----------------
extern "C" void kernel_launch(void* const* d_in, const int* in_sizes, int n_in,
                              void* d_out, int out_size) {
    const float* x     = (const float*)d_in[0];
    const float* w_qkv = (const float*)d_in[1];
    const float* w_dw3 = (const float*)d_in[2];
    const float* w_dw5 = (const float*)d_in[3];
    const float* w_dw7 = (const float*)d_in[4];
    const float* w_q   = (const float*)d_in[5];
    const float* w_k   = (const float*)d_in[6];
    const float* w_v   = (const float*)d_in[7];
    const float* w_out = (const float*)d_in[8];
    const float* temp  = (const float*)d_in[9];
    float* out = (float*)d_out;

    float *p_xq, *p_gram, *p_ssq, *p_ssk, *p_attn, *p_T1, *p_M;
    bf16 *p_xh, *p_xl, *p_Dh, *p_Dl, *p_wqkvh, *p_wqkvl, *p_wqh, *p_wql, *p_wkh, *p_wkl, *p_Mh, *p_Ml;
    cudaGetSymbolAddress((void**)&p_xq, g_xq);
    cudaGetSymbolAddress((void**)&p_xh, g_xh);
    cudaGetSymbolAddress((void**)&p_xl, g_xl);
    cudaGetSymbolAddress((void**)&p_Dh, g_Dh);
    cudaGetSymbolAddress((void**)&p_Dl, g_Dl);
    cudaGetSymbolAddress((void**)&p_gram, g_gram);
    cudaGetSymbolAddress((void**)&p_ssq, g_ssq);
    cudaGetSymbolAddress((void**)&p_ssk, g_ssk);
    cudaGetSymbolAddress((void**)&p_attn, g_attn);
    cudaGetSymbolAddress((void**)&p_T1, g_T1);
    cudaGetSymbolAddress((void**)&p_M, g_M);
    cudaGetSymbolAddress((void**)&p_wqkvh, g_wqkv_h);
    cudaGetSymbolAddress((void**)&p_wqkvl, g_wqkv_l);
    cudaGetSymbolAddress((void**)&p_wqh, g_wq_h);
    cudaGetSymbolAddress((void**)&p_wql, g_wq_l);
    cudaGetSymbolAddress((void**)&p_wkh, g_wk_h);
    cudaGetSymbolAddress((void**)&p_wkl, g_wk_l);
    cudaGetSymbolAddress((void**)&p_Mh, g_Mh);
    cudaGetSymbolAddress((void**)&p_Ml, g_Ml);

    cudaFuncSetAttribute(tc_gemm, cudaFuncAttributeMaxDynamicSharedMemorySize, STG_BYTES);
    cudaFuncSetAttribute(qk_gram, cudaFuncAttributeMaxDynamicSharedMemorySize, QKG_BYTES);

    // launch order arranged so ncu (-s 5 -c 1) captures gemm1 (launch idx 5)
    zero_stats<<<64, 256>>>(p_gram, p_ssq, p_ssk);                               // 0
    {
        int n4 = BATCH * CB * HWSZ / 4;
        cvt_split<<<(n4 + 255) / 256, 256>>>(x, p_xh, p_xl, n4);                 // 1
    }
    cvt_split<<<48, 256>>>(w_qkv, p_wqkvh, p_wqkvl, C3 * CB / 4);                // 2
    cvt_split<<<48, 256>>>(w_q, p_wqh, p_wql, CB * C3 / 4);                      // 3
    cvt_split<<<48, 256>>>(w_k, p_wkh, p_wkl, CB * C3 / 4);                      // 4

    // 1) xq = w_qkv @ x  (M=384, K=128); m fastest -> B shared in L2
    tc_gemm<<<dim3(3, 128, BATCH), 256, STG_BYTES>>>(                            // 5
        p_wqkvh, p_wqkvl, 128, (size_t)0,
        p_xh, p_xl, (size_t)CB * HWSZ, (size_t)CB * HWSZ,
        p_xq, (size_t)C3 * HWSZ);

    // 2) depthwise conv -> D hi/lo
    dwconv_kernel<<<dim3(2, 8, BATCH * C3), 256>>>(p_xq, w_dw3, w_dw5, w_dw7, p_Dh, p_Dl);

    // 3+4) fused q/k projections + gram + sumsq (q,k never hit DRAM)
    qk_gram<<<dim3(128, BATCH), 256, QKG_BYTES>>>(
        p_wqh, p_wql, p_wkh, p_wkl, p_Dh, p_Dl, p_gram, p_ssq, p_ssk);

    attn_finalize<<<BATCH * HEADS, 32>>>(p_gram, p_ssq, p_ssk, temp, p_attn);

    // 5) M_b = w_out @ blockdiag(attn) @ w_v  -> bf16 split
    t1_kernel<<<BATCH * CB, 384>>>(p_attn, w_v, p_T1);
    m_kernel<<<BATCH * CB, 384>>>(w_out, p_T1, p_M);
    cvt_split<<<384, 256>>>(p_M, p_Mh, p_Ml, BATCH * CB * C3 / 4);

    // 6) out = M_b @ D(v-part)  (M=128, K=384)
    tc_gemm<<<dim3(1, 128, BATCH), 256, STG_BYTES>>>(
        p_Mh, p_Ml, 384, (size_t)CB * C3,
        p_Dh + (size_t)2 * CB * HWSZ, p_Dl + (size_t)2 * CB * HWSZ, (size_t)3 * C3 * HWSZ, (size_t)C3 * HWSZ,
        out, (size_t)CB * HWSZ);
}

// round 8
// speedup vs baseline: 2.2594x; 1.1688x over previous
#include <cuda_runtime.h>
#include <cuda_fp16.h>
#include <cstddef>
#include <cstdint>
#include <math.h>

#define HWSZ 16384
#define IMG 128
#define CB 128
#define C3 384
#define BATCH 8
#define HEADS 8
#define KCH 32

typedef __half f16;

// smem: A [2buf][2pl][128][40] f16, B [2buf][32][136] f16
#define SA_ROW 40
#define SB_ROW 136
#define SA_PLANE (128 * SA_ROW)          // 5120
#define SB_PLANE (32 * SB_ROW)           // 4352
#define SA_ELEMS (4 * SA_PLANE)          // 20480
#define SB_ELEMS (2 * SB_PLANE)          // 8704
#define STG_H (SA_ELEMS + SB_ELEMS)      // 29184 halves
#define STG_BYTES (STG_H * 2)            // 58368
#define QREG_H 33792                     // 67584 B region (>= STG_H, >= 128*132*4/2)
#define QKG_BYTES (2 * QREG_H * 2)       // 135168

// ---------------- scratch ----------------
__device__ __align__(128) f16 g_x16[(size_t)BATCH * CB * HWSZ];
__device__ __align__(128) f16 g_xq16[(size_t)BATCH * C3 * HWSZ];
__device__ __align__(128) f16 g_D16[(size_t)BATCH * 3 * C3 * HWSZ];
__device__ __align__(128) f16 g_wqkv_h[C3 * CB], g_wqkv_l[C3 * CB];
__device__ __align__(128) f16 g_wq_h[CB * C3], g_wq_l[CB * C3];
__device__ __align__(128) f16 g_wk_h[CB * C3], g_wk_l[CB * C3];
__device__ __align__(128) f16 g_Mh[BATCH * CB * C3], g_Ml[BATCH * CB * C3];
__device__ float g_gram[BATCH * HEADS * 256];
__device__ float g_ssq[BATCH * HEADS * 16];
__device__ float g_ssk[BATCH * HEADS * 16];
__device__ float g_attn[BATCH * HEADS * 256];
__device__ float g_T1[BATCH * CB * C3];
__device__ float g_M[BATCH * CB * C3];

// ---------------- helpers ----------------
__device__ __forceinline__ uint32_t smem_u32(const void* p) {
    uint32_t a;
    asm("{ .reg .u64 t; cvta.to.shared.u64 t, %1; cvt.u32.u64 %0, t; }" : "=r"(a) : "l"(p));
    return a;
}
__device__ __forceinline__ void ldm_x4(uint32_t* r, uint32_t addr) {
    asm volatile("ldmatrix.sync.aligned.m8n8.x4.shared.b16 {%0,%1,%2,%3}, [%4];"
                 : "=r"(r[0]), "=r"(r[1]), "=r"(r[2]), "=r"(r[3]) : "r"(addr));
}
__device__ __forceinline__ void ldm_x2t(uint32_t* r, uint32_t addr) {
    asm volatile("ldmatrix.sync.aligned.m8n8.x2.trans.shared.b16 {%0,%1}, [%2];"
                 : "=r"(r[0]), "=r"(r[1]) : "r"(addr));
}
__device__ __forceinline__ void mma16816(float* d, const uint32_t* a, const uint32_t* b) {
    asm volatile(
        "mma.sync.aligned.m16n8k16.row.col.f32.f16.f16.f32 "
        "{%0,%1,%2,%3}, {%4,%5,%6,%7}, {%8,%9}, {%0,%1,%2,%3};"
        : "+f"(d[0]), "+f"(d[1]), "+f"(d[2]), "+f"(d[3])
        : "r"(a[0]), "r"(a[1]), "r"(a[2]), "r"(a[3]), "r"(b[0]), "r"(b[1]));
}

// ---- HMMA mainloop: acc += (Ah+Al)·B, 128m x 128n tile, fp16 2-term ----
// A row-major [.][Ktot] (hi/lo planes); B row r at B + (r>>7)*sStr + (r&127)*HWSZ, +n0.
__device__ __forceinline__ void gemm_mainloop(
    const f16* __restrict__ Ahb, const f16* __restrict__ Alb, int Ktot, int m0,
    const f16* __restrict__ Bb, size_t sStr, int n0,
    f16* sA, f16* sB, int tid, int wid, int lid, float acc[4][4][4]) {
    const int wm = (wid >> 2) * 64, wn = (wid & 3) * 32;
    const int nchunks = Ktot / KCH;

    // stage chunk 0 into buf 0
#pragma unroll
    for (int i = 0; i < 4; i++) {
        int u = tid + i * 256;                 // 1024 16B units (2 planes)
        int pl = u >> 9, v = u & 511;
        int m = v >> 2, kq = v & 3;
        const f16* src = (pl ? Alb : Ahb) + (size_t)(m0 + m) * Ktot + kq * 8;
        *(uint4*)(sA + pl * SA_PLANE + m * SA_ROW + kq * 8) = *(const uint4*)src;
    }
#pragma unroll
    for (int i = 0; i < 2; i++) {
        int u = tid + i * 256;                 // 512 16B units
        int k = u >> 4, nu = u & 15;
        *(uint4*)(sB + k * SB_ROW + nu * 8) =
            *(const uint4*)(Bb + (size_t)(k >> 7) * sStr + (size_t)(k & 127) * HWSZ + n0 + nu * 8);
    }
    __syncthreads();

    int buf = 0;
#pragma unroll 1
    for (int ch = 0; ch < nchunks; ch++) {
        const bool more = (ch + 1) < nchunks;
        uint4 pa[4], pb[2];
        if (more) {
            const int k0 = (ch + 1) * KCH;
#pragma unroll
            for (int i = 0; i < 4; i++) {
                int u = tid + i * 256;
                int pl = u >> 9, v = u & 511;
                int m = v >> 2, kq = v & 3;
                pa[i] = *(const uint4*)((pl ? Alb : Ahb) + (size_t)(m0 + m) * Ktot + k0 + kq * 8);
            }
#pragma unroll
            for (int i = 0; i < 2; i++) {
                int u = tid + i * 256;
                int k = u >> 4, nu = u & 15;
                int r = k0 + k;
                pb[i] = *(const uint4*)(Bb + (size_t)(r >> 7) * sStr +
                                        (size_t)(r & 127) * HWSZ + n0 + nu * 8);
            }
        }

        const uint32_t aBase0 = smem_u32(sA + (buf * 2 + 0) * SA_PLANE);
        const uint32_t aBase1 = smem_u32(sA + (buf * 2 + 1) * SA_PLANE);
        const uint32_t bBase = smem_u32(sB + buf * SB_PLANE);
#pragma unroll
        for (int k16 = 0; k16 < 2; k16++) {
            const int kk = k16 * 16;
            uint32_t aF[2][4][4], bF[4][2];
            const uint32_t aOff =
                ((uint32_t)((wm + (lid & 15)) * SA_ROW + kk + ((lid >> 4) << 3))) * 2;
#pragma unroll
            for (int mb = 0; mb < 4; mb++) {
                ldm_x4(aF[0][mb], aBase0 + aOff + mb * 16 * SA_ROW * 2);
                ldm_x4(aF[1][mb], aBase1 + aOff + mb * 16 * SA_ROW * 2);
            }
            const uint32_t bOff = ((uint32_t)((kk + (lid & 15)) * SB_ROW + wn)) * 2;
#pragma unroll
            for (int nb = 0; nb < 4; nb++) ldm_x2t(bF[nb], bBase + bOff + nb * 16);
#pragma unroll
            for (int mb = 0; mb < 4; mb++)
#pragma unroll
                for (int nb = 0; nb < 4; nb++) {
                    mma16816(acc[mb][nb], aF[0][mb], bF[nb]);
                    mma16816(acc[mb][nb], aF[1][mb], bF[nb]);
                }
        }
        __syncthreads();

        if (more) {
            const int nb2 = buf ^ 1;
#pragma unroll
            for (int i = 0; i < 4; i++) {
                int u = tid + i * 256;
                int pl = u >> 9, v = u & 511;
                int m = v >> 2, kq = v & 3;
                *(uint4*)(sA + (nb2 * 2 + pl) * SA_PLANE + m * SA_ROW + kq * 8) = pa[i];
            }
#pragma unroll
            for (int i = 0; i < 2; i++) {
                int u = tid + i * 256;
                int k = u >> 4, nu = u & 15;
                *(uint4*)(sB + nb2 * SB_PLANE + k * SB_ROW + nu * 8) = pb[i];  // FIXED
            }
            __syncthreads();
            buf = nb2;
        }
    }
}

// ================= GEMM, fp32 output (out-gemm) =================
__global__ void __launch_bounds__(256, 1)
tc_gemm_f32(const f16* __restrict__ Ah, const f16* __restrict__ Al, int Ktot, size_t aStr,
            const f16* __restrict__ B, size_t bStr, size_t sStr,
            float* __restrict__ C, size_t cStr) {
    extern __shared__ f16 dsm[];
    f16* sA = dsm;
    f16* sB = dsm + SA_ELEMS;
    const int tid = threadIdx.x, wid = tid >> 5, lid = tid & 31;
    const int m0 = blockIdx.x * 128, n0 = blockIdx.y * 128, b = blockIdx.z;
    const int wm = (wid >> 2) * 64, wn = (wid & 3) * 32;

    float acc[4][4][4];
#pragma unroll
    for (int i = 0; i < 4; i++)
#pragma unroll
        for (int j = 0; j < 4; j++)
#pragma unroll
            for (int t = 0; t < 4; t++) acc[i][j][t] = 0.f;

    gemm_mainloop(Ah + (size_t)b * aStr, Al + (size_t)b * aStr, Ktot, m0,
                  B + (size_t)b * bStr, sStr, n0, sA, sB, tid, wid, lid, acc);

    float* Cp = C + (size_t)b * cStr;
    const int g = lid >> 2, t = lid & 3;
#pragma unroll
    for (int mb = 0; mb < 4; mb++)
#pragma unroll
        for (int nb = 0; nb < 4; nb++) {
            int m = m0 + wm + mb * 16 + g;
            int n = n0 + wn + nb * 8 + t * 2;
            *(float2*)&Cp[(size_t)m * HWSZ + n] = make_float2(acc[mb][nb][0], acc[mb][nb][1]);
            *(float2*)&Cp[(size_t)(m + 8) * HWSZ + n] = make_float2(acc[mb][nb][2], acc[mb][nb][3]);
        }
}

// ================= GEMM, fp16 output (gemm1 -> xq16) =================
__global__ void __launch_bounds__(256, 1)
tc_gemm_f16(const f16* __restrict__ Ah, const f16* __restrict__ Al, int Ktot, size_t aStr,
            const f16* __restrict__ B, size_t bStr, size_t sStr,
            f16* __restrict__ C, size_t cStr) {
    extern __shared__ f16 dsm[];
    f16* sA = dsm;
    f16* sB = dsm + SA_ELEMS;
    const int tid = threadIdx.x, wid = tid >> 5, lid = tid & 31;
    const int m0 = blockIdx.x * 128, n0 = blockIdx.y * 128, b = blockIdx.z;
    const int wm = (wid >> 2) * 64, wn = (wid & 3) * 32;

    float acc[4][4][4];
#pragma unroll
    for (int i = 0; i < 4; i++)
#pragma unroll
        for (int j = 0; j < 4; j++)
#pragma unroll
            for (int t = 0; t < 4; t++) acc[i][j][t] = 0.f;

    gemm_mainloop(Ah + (size_t)b * aStr, Al + (size_t)b * aStr, Ktot, m0,
                  B + (size_t)b * bStr, sStr, n0, sA, sB, tid, wid, lid, acc);

    f16* Cp = C + (size_t)b * cStr;
    const int g = lid >> 2, t = lid & 3;
#pragma unroll
    for (int mb = 0; mb < 4; mb++)
#pragma unroll
        for (int nb = 0; nb < 4; nb++) {
            int m = m0 + wm + mb * 16 + g;
            int n = n0 + wn + nb * 8 + t * 2;
            __half2 v01 = __floats2half2_rn(acc[mb][nb][0], acc[mb][nb][1]);
            __half2 v23 = __floats2half2_rn(acc[mb][nb][2], acc[mb][nb][3]);
            *(__half2*)&Cp[(size_t)m * HWSZ + n] = v01;
            *(__half2*)&Cp[(size_t)(m + 8) * HWSZ + n] = v23;
        }
}

// ====== fused q-proj + k-proj + per-head gram/sumsq ======
__global__ void __launch_bounds__(256, 1)
qk_gram(const f16* __restrict__ wqh, const f16* __restrict__ wql,
        const f16* __restrict__ wkh, const f16* __restrict__ wkl,
        const f16* __restrict__ D,
        float* __restrict__ G, float* __restrict__ SQ, float* __restrict__ SK) {
    extern __shared__ f16 dsm[];
    f16* sA = dsm;
    f16* sB = dsm + SA_ELEMS;
    float* qst = (float*)(dsm + QREG_H);   // [128 n][132] transposed q
    float* kst = (float*)dsm;              // reuses staging region after phase B

    const int tid = threadIdx.x, wid = tid >> 5, lid = tid & 31;
    const int n0 = blockIdx.x * 128, b = blockIdx.y;
    const int wm = (wid >> 2) * 64, wn = (wid & 3) * 32;
    const int g = lid >> 2, t4 = lid & 3;

    const f16* Db = D + (size_t)b * 3 * C3 * HWSZ;

    float acc[4][4][4];
#pragma unroll
    for (int i = 0; i < 4; i++)
#pragma unroll
        for (int j = 0; j < 4; j++)
#pragma unroll
            for (int t = 0; t < 4; t++) acc[i][j][t] = 0.f;

    // ---- phase A: q tile ----
    gemm_mainloop(wqh, wql, C3, 0, Db, (size_t)C3 * HWSZ, n0, sA, sB, tid, wid, lid, acc);
#pragma unroll
    for (int mb = 0; mb < 4; mb++)
#pragma unroll
        for (int nb = 0; nb < 4; nb++) {
            int m = wm + mb * 16 + g;
            int n = wn + nb * 8 + t4 * 2;
            qst[n * 132 + m] = acc[mb][nb][0];
            qst[(n + 1) * 132 + m] = acc[mb][nb][1];
            qst[n * 132 + m + 8] = acc[mb][nb][2];
            qst[(n + 1) * 132 + m + 8] = acc[mb][nb][3];
            acc[mb][nb][0] = acc[mb][nb][1] = acc[mb][nb][2] = acc[mb][nb][3] = 0.f;
        }
    __syncthreads();

    // ---- phase B: k tile ----
    gemm_mainloop(wkh, wkl, C3, 0, Db + (size_t)CB * HWSZ, (size_t)C3 * HWSZ, n0,
                  sA, sB, tid, wid, lid, acc);
    __syncthreads();
#pragma unroll
    for (int mb = 0; mb < 4; mb++)
#pragma unroll
        for (int nb = 0; nb < 4; nb++) {
            int m = wm + mb * 16 + g;
            int n = wn + nb * 8 + t4 * 2;
            kst[n * 132 + m] = acc[mb][nb][0];
            kst[(n + 1) * 132 + m] = acc[mb][nb][1];
            kst[n * 132 + m + 8] = acc[mb][nb][2];
            kst[(n + 1) * 132 + m + 8] = acc[mb][nb][3];
        }
    __syncthreads();

    // ---- phase C: per-head gram + sumsq ----
    {
        const int h = wid;
        const int c = lid >> 1;
        const int d0 = (lid & 1) * 8;
        float a8[8] = {0, 0, 0, 0, 0, 0, 0, 0};
        float sq = 0.f, sk8[8] = {0, 0, 0, 0, 0, 0, 0, 0};
#pragma unroll 4
        for (int n = 0; n < 128; n++) {
            float qv = qst[n * 132 + h * 16 + c];
            float4 k0 = *(float4*)&kst[n * 132 + h * 16 + d0];
            float4 k1 = *(float4*)&kst[n * 132 + h * 16 + d0 + 4];
            a8[0] += qv * k0.x; a8[1] += qv * k0.y; a8[2] += qv * k0.z; a8[3] += qv * k0.w;
            a8[4] += qv * k1.x; a8[5] += qv * k1.y; a8[6] += qv * k1.z; a8[7] += qv * k1.w;
            if ((lid & 1) == 0) sq += qv * qv;
            if (c == 0) {
                sk8[0] += k0.x * k0.x; sk8[1] += k0.y * k0.y;
                sk8[2] += k0.z * k0.z; sk8[3] += k0.w * k0.w;
                sk8[4] += k1.x * k1.x; sk8[5] += k1.y * k1.y;
                sk8[6] += k1.z * k1.z; sk8[7] += k1.w * k1.w;
            }
        }
        const int bh = b * HEADS + h;
#pragma unroll
        for (int j = 0; j < 8; j++)
            atomicAdd(&G[(size_t)bh * 256 + c * 16 + d0 + j], a8[j]);
        if ((lid & 1) == 0) atomicAdd(&SQ[bh * 16 + c], sq);
        if (c == 0)
#pragma unroll
            for (int j = 0; j < 8; j++) atomicAdd(&SK[bh * 16 + d0 + j], sk8[j]);
    }
}

// ---------------- converters ----------------
__global__ void cvt_f16(const float* __restrict__ src, f16* __restrict__ dst, int n4) {
    int i = blockIdx.x * 256 + threadIdx.x;
    if (i >= n4) return;
    float4 v = ((const float4*)src)[i];
    f16 h[4] = {__float2half_rn(v.x), __float2half_rn(v.y),
                __float2half_rn(v.z), __float2half_rn(v.w)};
    ((uint2*)dst)[i] = *(uint2*)h;
}

__device__ __forceinline__ void split_store(const float4& v, f16* hi, f16* lo, int i) {
    float a[4] = {v.x, v.y, v.z, v.w};
    f16 h[4], l[4];
#pragma unroll
    for (int j = 0; j < 4; j++) {
        h[j] = __float2half_rn(a[j]);
        l[j] = __float2half_rn(a[j] - __half2float(h[j]));
    }
    ((uint2*)hi)[i] = *(uint2*)h;
    ((uint2*)lo)[i] = *(uint2*)l;
}

__global__ void cvt_split_h(const float* __restrict__ src, f16* __restrict__ hi,
                            f16* __restrict__ lo, int n4) {
    int i = blockIdx.x * 256 + threadIdx.x;
    if (i >= n4) return;
    split_store(((const float4*)src)[i], hi, lo, i);
}

__global__ void cvt_wqk(const float* __restrict__ wq, const float* __restrict__ wk,
                        f16* __restrict__ qh, f16* __restrict__ ql,
                        f16* __restrict__ kh, f16* __restrict__ kl, int n4) {
    int i = blockIdx.x * 256 + threadIdx.x;
    if (i >= n4) return;
    if (blockIdx.y == 0) split_store(((const float4*)wq)[i], qh, ql, i);
    else                 split_store(((const float4*)wk)[i], kh, kl, i);
}

// ---------------- fused depthwise conv (fp16 in/out) ----------------
__global__ void __launch_bounds__(256)
dwconv_kernel(const f16* __restrict__ xq, const float* __restrict__ w3,
              const float* __restrict__ w5, const float* __restrict__ w7,
              f16* __restrict__ D) {
    __shared__ float tile[22][72];
    __shared__ float s3[9], s5[25], s7[49];

    const int bc = blockIdx.z;
    const int b = bc / C3, c = bc % C3;
    const int x0 = blockIdx.x * 64, y0 = blockIdx.y * 16;
    const int tid = threadIdx.x;

    const f16* src = xq + (size_t)bc * HWSZ;
    if (tid < 9) s3[tid] = w3[c * 9 + tid];
    if (tid < 25) s5[tid] = w5[c * 25 + tid];
    if (tid < 49) s7[tid] = w7[c * 49 + tid];

    for (int e = tid; e < 22 * 70; e += 256) {
        int iy = e / 70, ix = e % 70;
        int gy = y0 - 3 + iy, gx = x0 - 3 + ix;
        float v = 0.f;
        if (gy >= 0 && gy < IMG && gx >= 0 && gx < IMG) v = __half2float(src[gy * IMG + gx]);
        tile[iy][ix] = v;
    }
    __syncthreads();

    const int ty = tid >> 4, tx = (tid & 15) * 4;
    float a3[4] = {0, 0, 0, 0}, a5[4] = {0, 0, 0, 0}, a7[4] = {0, 0, 0, 0};
#pragma unroll
    for (int ky = 0; ky < 7; ky++) {
        float r[10];
#pragma unroll
        for (int j = 0; j < 10; j++) r[j] = tile[ty + ky][tx + j];
#pragma unroll
        for (int kx = 0; kx < 7; kx++) {
            float w = s7[ky * 7 + kx];
#pragma unroll
            for (int xi = 0; xi < 4; xi++) a7[xi] += r[kx + xi] * w;
        }
        if (ky >= 1 && ky <= 5) {
#pragma unroll
            for (int kx = 0; kx < 5; kx++) {
                float w = s5[(ky - 1) * 5 + kx];
#pragma unroll
                for (int xi = 0; xi < 4; xi++) a5[xi] += r[kx + 1 + xi] * w;
            }
        }
        if (ky >= 2 && ky <= 4) {
#pragma unroll
            for (int kx = 0; kx < 3; kx++) {
                float w = s3[(ky - 2) * 3 + kx];
#pragma unroll
                for (int xi = 0; xi < 4; xi++) a3[xi] += r[kx + 2 + xi] * w;
            }
        }
    }

    size_t o = ((size_t)b * 3 * C3 + c) * HWSZ + (size_t)(y0 + ty) * IMG + (x0 + tx);
    f16 h3[4] = {__float2half_rn(a3[0]), __float2half_rn(a3[1]),
                 __float2half_rn(a3[2]), __float2half_rn(a3[3])};
    f16 h5[4] = {__float2half_rn(a5[0]), __float2half_rn(a5[1]),
                 __float2half_rn(a5[2]), __float2half_rn(a5[3])};
    f16 h7[4] = {__float2half_rn(a7[0]), __float2half_rn(a7[1]),
                 __float2half_rn(a7[2]), __float2half_rn(a7[3])};
    *(uint2*)&D[o] = *(uint2*)h3;
    *(uint2*)&D[o + (size_t)C3 * HWSZ] = *(uint2*)h5;
    *(uint2*)&D[o + (size_t)2 * C3 * HWSZ] = *(uint2*)h7;
}

// ---------------- softmax finalize ----------------
__global__ void attn_finalize(const float* __restrict__ G, const float* __restrict__ SQ,
                              const float* __restrict__ SK, const float* __restrict__ temp,
                              float* __restrict__ attn) {
    const int bh = blockIdx.x, h = bh & 7, c = threadIdx.x;
    if (c >= 16) return;
    float nq = fmaxf(sqrtf(SQ[bh * 16 + c]), 1e-12f);
    float t = temp[h];
    float s[16], mx = -1e30f;
#pragma unroll
    for (int d = 0; d < 16; d++) {
        float nk = fmaxf(sqrtf(SK[bh * 16 + d]), 1e-12f);
        s[d] = G[bh * 256 + c * 16 + d] / (nq * nk) * t;
        mx = fmaxf(mx, s[d]);
    }
    float sum = 0.f;
#pragma unroll
    for (int d = 0; d < 16; d++) { s[d] = expf(s[d] - mx); sum += s[d]; }
    float inv = 1.f / sum;
#pragma unroll
    for (int d = 0; d < 16; d++) attn[bh * 256 + c * 16 + d] = s[d] * inv;
}

// ---------------- T1 / M ----------------
__global__ void t1_kernel(const float* __restrict__ attn, const float* __restrict__ wv,
                          float* __restrict__ T1) {
    const int bm = blockIdx.x, b = bm >> 7, m = bm & 127, h = m >> 4, cm = m & 15;
    __shared__ float a[16];
    if (threadIdx.x < 16) a[threadIdx.x] = attn[((b * 8 + h) * 16 + cm) * 16 + threadIdx.x];
    __syncthreads();
    const int r = threadIdx.x;
    float acc = 0.f;
#pragma unroll
    for (int d = 0; d < 16; d++) acc += a[d] * wv[(h * 16 + d) * C3 + r];
    T1[((size_t)b * CB + m) * C3 + r] = acc;
}

__global__ void m_kernel(const float* __restrict__ wout, const float* __restrict__ T1,
                         float* __restrict__ Mo) {
    const int bo = blockIdx.x, b = bo >> 7, o = bo & 127;
    __shared__ float w[128];
    if (threadIdx.x < 128) w[threadIdx.x] = wout[o * 128 + threadIdx.x];
    __syncthreads();
    const int r = threadIdx.x;
    float acc = 0.f;
#pragma unroll 8
    for (int m = 0; m < 128; m++) acc += w[m] * T1[((size_t)b * CB + m) * C3 + r];
    Mo[((size_t)b * CB + o) * C3 + r] = acc;
}

__global__ void zero_stats(float* __restrict__ G, float* __restrict__ SQ,
                           float* __restrict__ SK) {
    int i = blockIdx.x * 256 + threadIdx.x;
    if (i < BATCH * HEADS * 256) G[i] = 0.f;
    if (i < BATCH * HEADS * 16) { SQ[i] = 0.f; SK[i] = 0.f; }
}

// ---------------- host launcher ----------------
extern "C" void kernel_launch(void* const* d_in, const int* in_sizes, int n_in,
                              void* d_out, int out_size) {
    const float* x     = (const float*)d_in[0];
    const float* w_qkv = (const float*)d_in[1];
    const float* w_dw3 = (const float*)d_in[2];
    const float* w_dw5 = (const float*)d_in[3];
    const float* w_dw7 = (const float*)d_in[4];
    const float* w_q   = (const float*)d_in[5];
    const float* w_k   = (const float*)d_in[6];
    const float* w_v   = (const float*)d_in[7];
    const float* w_out = (const float*)d_in[8];
    const float* temp  = (const float*)d_in[9];
    float* out = (float*)d_out;

    float *p_gram, *p_ssq, *p_ssk, *p_attn, *p_T1, *p_M;
    f16 *p_x16, *p_xq16, *p_D16, *p_wqkvh, *p_wqkvl, *p_wqh, *p_wql, *p_wkh, *p_wkl, *p_Mh, *p_Ml;
    cudaGetSymbolAddress((void**)&p_x16, g_x16);
    cudaGetSymbolAddress((void**)&p_xq16, g_xq16);
    cudaGetSymbolAddress((void**)&p_D16, g_D16);
    cudaGetSymbolAddress((void**)&p_gram, g_gram);
    cudaGetSymbolAddress((void**)&p_ssq, g_ssq);
    cudaGetSymbolAddress((void**)&p_ssk, g_ssk);
    cudaGetSymbolAddress((void**)&p_attn, g_attn);
    cudaGetSymbolAddress((void**)&p_T1, g_T1);
    cudaGetSymbolAddress((void**)&p_M, g_M);
    cudaGetSymbolAddress((void**)&p_wqkvh, g_wqkv_h);
    cudaGetSymbolAddress((void**)&p_wqkvl, g_wqkv_l);
    cudaGetSymbolAddress((void**)&p_wqh, g_wq_h);
    cudaGetSymbolAddress((void**)&p_wql, g_wq_l);
    cudaGetSymbolAddress((void**)&p_wkh, g_wk_h);
    cudaGetSymbolAddress((void**)&p_wkl, g_wk_l);
    cudaGetSymbolAddress((void**)&p_Mh, g_Mh);
    cudaGetSymbolAddress((void**)&p_Ml, g_Ml);

    cudaFuncSetAttribute(tc_gemm_f32, cudaFuncAttributeMaxDynamicSharedMemorySize, STG_BYTES);
    cudaFuncSetAttribute(tc_gemm_f16, cudaFuncAttributeMaxDynamicSharedMemorySize, STG_BYTES);
    cudaFuncSetAttribute(qk_gram, cudaFuncAttributeMaxDynamicSharedMemorySize, QKG_BYTES);

    // launch order: gemm1 at our idx 4 so ncu (-s 5 -c 1) captures it.
    zero_stats<<<64, 256>>>(p_gram, p_ssq, p_ssk);                              // 0
    {
        int n4 = BATCH * CB * HWSZ / 4;
        cvt_f16<<<(n4 + 255) / 256, 256>>>(x, p_x16, n4);                       // 1
    }
    cvt_split_h<<<48, 256>>>(w_qkv, p_wqkvh, p_wqkvl, C3 * CB / 4);             // 2
    cvt_wqk<<<dim3(48, 2), 256>>>(w_q, w_k, p_wqh, p_wql, p_wkh, p_wkl, CB * C3 / 4);  // 3

    // 1) xq = w_qkv @ x  (M=384, K=128) -> fp16
    tc_gemm_f16<<<dim3(3, 128, BATCH), 256, STG_BYTES>>>(                       // 4
        p_wqkvh, p_wqkvl, 128, (size_t)0,
        p_x16, (size_t)CB * HWSZ, (size_t)CB * HWSZ,
        p_xq16, (size_t)C3 * HWSZ);

    // 2) depthwise conv -> D fp16
    dwconv_kernel<<<dim3(2, 8, BATCH * C3), 256>>>(p_xq16, w_dw3, w_dw5, w_dw7, p_D16);

    // 3) fused q/k projections + gram + sumsq
    qk_gram<<<dim3(128, BATCH), 256, QKG_BYTES>>>(
        p_wqh, p_wql, p_wkh, p_wkl, p_D16, p_gram, p_ssq, p_ssk);

    attn_finalize<<<BATCH * HEADS, 32>>>(p_gram, p_ssq, p_ssk, temp, p_attn);

    // 4) M_b = w_out @ blockdiag(attn) @ w_v -> fp16 split
    t1_kernel<<<BATCH * CB, 384>>>(p_attn, w_v, p_T1);
    m_kernel<<<BATCH * CB, 384>>>(w_out, p_T1, p_M);
    cvt_split_h<<<384, 256>>>(p_M, p_Mh, p_Ml, BATCH * CB * C3 / 4);

    // 5) out = M_b @ D(v-part)  (M=128, K=384)
    tc_gemm_f32<<<dim3(1, 128, BATCH), 256, STG_BYTES>>>(
        p_Mh, p_Ml, 384, (size_t)CB * C3,
        p_D16 + (size_t)2 * CB * HWSZ, (size_t)3 * C3 * HWSZ, (size_t)C3 * HWSZ,
        out, (size_t)CB * HWSZ);
}

// round 9
// speedup vs baseline: 2.4243x; 1.0730x over previous
#include <cuda_runtime.h>
#include <cuda_fp16.h>
#include <cstddef>
#include <cstdint>
#include <math.h>

#define HWSZ 16384
#define IMG 128
#define CB 128
#define C3 384
#define BATCH 8
#define HEADS 8
#define KCH 32

typedef __half f16;

// smem: A [2buf][2pl][128][40] f16, B [2buf][32][136] f16
#define SA_ROW 40
#define SB_ROW 136
#define SA_PLANE (128 * SA_ROW)          // 5120
#define SB_PLANE (32 * SB_ROW)           // 4352
#define SA_ELEMS (4 * SA_PLANE)          // 20480
#define SB_ELEMS (2 * SB_PLANE)          // 8704
#define STG_H (SA_ELEMS + SB_ELEMS)      // 29184 halves
#define STG_BYTES (STG_H * 2)            // 58368
#define QREG_H 33792                     // 67584 B region (>= STG_H, >= 128*132*4/2)
#define QKG_BYTES (2 * QREG_H * 2)       // 135168

// ---------------- scratch ----------------
__device__ __align__(128) f16 g_x16[(size_t)BATCH * CB * HWSZ];
__device__ __align__(128) f16 g_xq16[(size_t)BATCH * C3 * HWSZ];
__device__ __align__(128) f16 g_D16[(size_t)BATCH * 3 * C3 * HWSZ];
__device__ __align__(128) f16 g_wqkv_h[C3 * CB], g_wqkv_l[C3 * CB];
__device__ __align__(128) f16 g_wq_h[CB * C3], g_wq_l[CB * C3];
__device__ __align__(128) f16 g_wk_h[CB * C3], g_wk_l[CB * C3];
__device__ __align__(128) f16 g_Mh[BATCH * CB * C3], g_Ml[BATCH * CB * C3];
__device__ float g_gram[BATCH * HEADS * 256];
__device__ float g_ssq[BATCH * HEADS * 16];
__device__ float g_ssk[BATCH * HEADS * 16];
__device__ float g_attn[BATCH * HEADS * 256];
__device__ float g_T1[BATCH * CB * C3];
__device__ float g_M[BATCH * CB * C3];

// ---------------- helpers ----------------
__device__ __forceinline__ uint32_t smem_u32(const void* p) {
    uint32_t a;
    asm("{ .reg .u64 t; cvta.to.shared.u64 t, %1; cvt.u32.u64 %0, t; }" : "=r"(a) : "l"(p));
    return a;
}
__device__ __forceinline__ void ldm_x4(uint32_t* r, uint32_t addr) {
    asm volatile("ldmatrix.sync.aligned.m8n8.x4.shared.b16 {%0,%1,%2,%3}, [%4];"
                 : "=r"(r[0]), "=r"(r[1]), "=r"(r[2]), "=r"(r[3]) : "r"(addr));
}
__device__ __forceinline__ void ldm_x2t(uint32_t* r, uint32_t addr) {
    asm volatile("ldmatrix.sync.aligned.m8n8.x2.trans.shared.b16 {%0,%1}, [%2];"
                 : "=r"(r[0]), "=r"(r[1]) : "r"(addr));
}
__device__ __forceinline__ void mma16816(float* d, const uint32_t* a, const uint32_t* b) {
    asm volatile(
        "mma.sync.aligned.m16n8k16.row.col.f32.f16.f16.f32 "
        "{%0,%1,%2,%3}, {%4,%5,%6,%7}, {%8,%9}, {%0,%1,%2,%3};"
        : "+f"(d[0]), "+f"(d[1]), "+f"(d[2]), "+f"(d[3])
        : "r"(a[0]), "r"(a[1]), "r"(a[2]), "r"(a[3]), "r"(b[0]), "r"(b[1]));
}

// ---- HMMA mainloop: acc += (Ah+Al)·B, 128m x 128n tile, fp16 2-term ----
// A row-major [.][Ktot] (hi/lo planes); B row r at B + (r>>7)*sStr + (r&127)*HWSZ, +n0.
__device__ __forceinline__ void gemm_mainloop(
    const f16* __restrict__ Ahb, const f16* __restrict__ Alb, int Ktot, int m0,
    const f16* __restrict__ Bb, size_t sStr, int n0,
    f16* sA, f16* sB, int tid, int wid, int lid, float acc[4][4][4]) {
    const int wm = (wid >> 2) * 64, wn = (wid & 3) * 32;
    const int nchunks = Ktot / KCH;

    // stage chunk 0 into buf 0
#pragma unroll
    for (int i = 0; i < 4; i++) {
        int u = tid + i * 256;                 // 1024 16B units (2 planes)
        int pl = u >> 9, v = u & 511;
        int m = v >> 2, kq = v & 3;
        const f16* src = (pl ? Alb : Ahb) + (size_t)(m0 + m) * Ktot + kq * 8;
        *(uint4*)(sA + pl * SA_PLANE + m * SA_ROW + kq * 8) = *(const uint4*)src;
    }
#pragma unroll
    for (int i = 0; i < 2; i++) {
        int u = tid + i * 256;                 // 512 16B units
        int k = u >> 4, nu = u & 15;
        *(uint4*)(sB + k * SB_ROW + nu * 8) =
            *(const uint4*)(Bb + (size_t)(k >> 7) * sStr + (size_t)(k & 127) * HWSZ + n0 + nu * 8);
    }
    __syncthreads();

    int buf = 0;
#pragma unroll 1
    for (int ch = 0; ch < nchunks; ch++) {
        const bool more = (ch + 1) < nchunks;
        uint4 pa[4], pb[2];
        if (more) {
            const int k0 = (ch + 1) * KCH;
#pragma unroll
            for (int i = 0; i < 4; i++) {
                int u = tid + i * 256;
                int pl = u >> 9, v = u & 511;
                int m = v >> 2, kq = v & 3;
                pa[i] = *(const uint4*)((pl ? Alb : Ahb) + (size_t)(m0 + m) * Ktot + k0 + kq * 8);
            }
#pragma unroll
            for (int i = 0; i < 2; i++) {
                int u = tid + i * 256;
                int k = u >> 4, nu = u & 15;
                int r = k0 + k;
                pb[i] = *(const uint4*)(Bb + (size_t)(r >> 7) * sStr +
                                        (size_t)(r & 127) * HWSZ + n0 + nu * 8);
            }
        }

        const uint32_t aBase0 = smem_u32(sA + (buf * 2 + 0) * SA_PLANE);
        const uint32_t aBase1 = smem_u32(sA + (buf * 2 + 1) * SA_PLANE);
        const uint32_t bBase = smem_u32(sB + buf * SB_PLANE);
#pragma unroll
        for (int k16 = 0; k16 < 2; k16++) {
            const int kk = k16 * 16;
            uint32_t aF[2][4][4], bF[4][2];
            const uint32_t aOff =
                ((uint32_t)((wm + (lid & 15)) * SA_ROW + kk + ((lid >> 4) << 3))) * 2;
#pragma unroll
            for (int mb = 0; mb < 4; mb++) {
                ldm_x4(aF[0][mb], aBase0 + aOff + mb * 16 * SA_ROW * 2);
                ldm_x4(aF[1][mb], aBase1 + aOff + mb * 16 * SA_ROW * 2);
            }
            const uint32_t bOff = ((uint32_t)((kk + (lid & 15)) * SB_ROW + wn)) * 2;
#pragma unroll
            for (int nb = 0; nb < 4; nb++) ldm_x2t(bF[nb], bBase + bOff + nb * 16);
#pragma unroll
            for (int mb = 0; mb < 4; mb++)
#pragma unroll
                for (int nb = 0; nb < 4; nb++) {
                    mma16816(acc[mb][nb], aF[0][mb], bF[nb]);
                    mma16816(acc[mb][nb], aF[1][mb], bF[nb]);
                }
        }
        __syncthreads();

        if (more) {
            const int nb2 = buf ^ 1;
#pragma unroll
            for (int i = 0; i < 4; i++) {
                int u = tid + i * 256;
                int pl = u >> 9, v = u & 511;
                int m = v >> 2, kq = v & 3;
                *(uint4*)(sA + (nb2 * 2 + pl) * SA_PLANE + m * SA_ROW + kq * 8) = pa[i];
            }
#pragma unroll
            for (int i = 0; i < 2; i++) {
                int u = tid + i * 256;
                int k = u >> 4, nu = u & 15;
                *(uint4*)(sB + nb2 * SB_PLANE + k * SB_ROW + nu * 8) = pb[i];
            }
            __syncthreads();
            buf = nb2;
        }
    }
}

// ================= GEMM, fp32 output (out-gemm) =================
__global__ void __launch_bounds__(256, 2)
tc_gemm_f32(const f16* __restrict__ Ah, const f16* __restrict__ Al, int Ktot, size_t aStr,
            const f16* __restrict__ B, size_t bStr, size_t sStr,
            float* __restrict__ C, size_t cStr) {
    extern __shared__ f16 dsm[];
    f16* sA = dsm;
    f16* sB = dsm + SA_ELEMS;
    const int tid = threadIdx.x, wid = tid >> 5, lid = tid & 31;
    const int m0 = blockIdx.x * 128, n0 = blockIdx.y * 128, b = blockIdx.z;
    const int wm = (wid >> 2) * 64, wn = (wid & 3) * 32;

    float acc[4][4][4];
#pragma unroll
    for (int i = 0; i < 4; i++)
#pragma unroll
        for (int j = 0; j < 4; j++)
#pragma unroll
            for (int t = 0; t < 4; t++) acc[i][j][t] = 0.f;

    gemm_mainloop(Ah + (size_t)b * aStr, Al + (size_t)b * aStr, Ktot, m0,
                  B + (size_t)b * bStr, sStr, n0, sA, sB, tid, wid, lid, acc);

    float* Cp = C + (size_t)b * cStr;
    const int g = lid >> 2, t = lid & 3;
#pragma unroll
    for (int mb = 0; mb < 4; mb++)
#pragma unroll
        for (int nb = 0; nb < 4; nb++) {
            int m = m0 + wm + mb * 16 + g;
            int n = n0 + wn + nb * 8 + t * 2;
            *(float2*)&Cp[(size_t)m * HWSZ + n] = make_float2(acc[mb][nb][0], acc[mb][nb][1]);
            *(float2*)&Cp[(size_t)(m + 8) * HWSZ + n] = make_float2(acc[mb][nb][2], acc[mb][nb][3]);
        }
}

// ================= GEMM, fp16 output (gemm1 -> xq16) =================
__global__ void __launch_bounds__(256, 2)
tc_gemm_f16(const f16* __restrict__ Ah, const f16* __restrict__ Al, int Ktot, size_t aStr,
            const f16* __restrict__ B, size_t bStr, size_t sStr,
            f16* __restrict__ C, size_t cStr) {
    extern __shared__ f16 dsm[];
    f16* sA = dsm;
    f16* sB = dsm + SA_ELEMS;
    const int tid = threadIdx.x, wid = tid >> 5, lid = tid & 31;
    const int m0 = blockIdx.x * 128, n0 = blockIdx.y * 128, b = blockIdx.z;
    const int wm = (wid >> 2) * 64, wn = (wid & 3) * 32;

    float acc[4][4][4];
#pragma unroll
    for (int i = 0; i < 4; i++)
#pragma unroll
        for (int j = 0; j < 4; j++)
#pragma unroll
            for (int t = 0; t < 4; t++) acc[i][j][t] = 0.f;

    gemm_mainloop(Ah + (size_t)b * aStr, Al + (size_t)b * aStr, Ktot, m0,
                  B + (size_t)b * bStr, sStr, n0, sA, sB, tid, wid, lid, acc);

    f16* Cp = C + (size_t)b * cStr;
    const int g = lid >> 2, t = lid & 3;
#pragma unroll
    for (int mb = 0; mb < 4; mb++)
#pragma unroll
        for (int nb = 0; nb < 4; nb++) {
            int m = m0 + wm + mb * 16 + g;
            int n = n0 + wn + nb * 8 + t * 2;
            __half2 v01 = __floats2half2_rn(acc[mb][nb][0], acc[mb][nb][1]);
            __half2 v23 = __floats2half2_rn(acc[mb][nb][2], acc[mb][nb][3]);
            *(__half2*)&Cp[(size_t)m * HWSZ + n] = v01;
            *(__half2*)&Cp[(size_t)(m + 8) * HWSZ + n] = v23;
        }
}

// ====== fused q-proj + k-proj + per-head gram/sumsq ======
__global__ void __launch_bounds__(256, 1)
qk_gram(const f16* __restrict__ wqh, const f16* __restrict__ wql,
        const f16* __restrict__ wkh, const f16* __restrict__ wkl,
        const f16* __restrict__ D,
        float* __restrict__ G, float* __restrict__ SQ, float* __restrict__ SK) {
    extern __shared__ f16 dsm[];
    f16* sA = dsm;
    f16* sB = dsm + SA_ELEMS;
    float* qst = (float*)(dsm + QREG_H);   // [128 n][132] transposed q
    float* kst = (float*)dsm;              // reuses staging region after phase B

    const int tid = threadIdx.x, wid = tid >> 5, lid = tid & 31;
    const int n0 = blockIdx.x * 128, b = blockIdx.y;
    const int wm = (wid >> 2) * 64, wn = (wid & 3) * 32;
    const int g = lid >> 2, t4 = lid & 3;

    const f16* Db = D + (size_t)b * 3 * C3 * HWSZ;

    float acc[4][4][4];
#pragma unroll
    for (int i = 0; i < 4; i++)
#pragma unroll
        for (int j = 0; j < 4; j++)
#pragma unroll
            for (int t = 0; t < 4; t++) acc[i][j][t] = 0.f;

    // ---- phase A: q tile ----
    gemm_mainloop(wqh, wql, C3, 0, Db, (size_t)C3 * HWSZ, n0, sA, sB, tid, wid, lid, acc);
#pragma unroll
    for (int mb = 0; mb < 4; mb++)
#pragma unroll
        for (int nb = 0; nb < 4; nb++) {
            int m = wm + mb * 16 + g;
            int n = wn + nb * 8 + t4 * 2;
            qst[n * 132 + m] = acc[mb][nb][0];
            qst[(n + 1) * 132 + m] = acc[mb][nb][1];
            qst[n * 132 + m + 8] = acc[mb][nb][2];
            qst[(n + 1) * 132 + m + 8] = acc[mb][nb][3];
            acc[mb][nb][0] = acc[mb][nb][1] = acc[mb][nb][2] = acc[mb][nb][3] = 0.f;
        }
    __syncthreads();

    // ---- phase B: k tile ----
    gemm_mainloop(wkh, wkl, C3, 0, Db + (size_t)CB * HWSZ, (size_t)C3 * HWSZ, n0,
                  sA, sB, tid, wid, lid, acc);
    __syncthreads();
#pragma unroll
    for (int mb = 0; mb < 4; mb++)
#pragma unroll
        for (int nb = 0; nb < 4; nb++) {
            int m = wm + mb * 16 + g;
            int n = wn + nb * 8 + t4 * 2;
            kst[n * 132 + m] = acc[mb][nb][0];
            kst[(n + 1) * 132 + m] = acc[mb][nb][1];
            kst[n * 132 + m + 8] = acc[mb][nb][2];
            kst[(n + 1) * 132 + m + 8] = acc[mb][nb][3];
        }
    __syncthreads();

    // ---- phase C: per-head gram + sumsq ----
    {
        const int h = wid;
        const int c = lid >> 1;
        const int d0 = (lid & 1) * 8;
        float a8[8] = {0, 0, 0, 0, 0, 0, 0, 0};
        float sq = 0.f, sk8[8] = {0, 0, 0, 0, 0, 0, 0, 0};
#pragma unroll 4
        for (int n = 0; n < 128; n++) {
            float qv = qst[n * 132 + h * 16 + c];
            float4 k0 = *(float4*)&kst[n * 132 + h * 16 + d0];
            float4 k1 = *(float4*)&kst[n * 132 + h * 16 + d0 + 4];
            a8[0] += qv * k0.x; a8[1] += qv * k0.y; a8[2] += qv * k0.z; a8[3] += qv * k0.w;
            a8[4] += qv * k1.x; a8[5] += qv * k1.y; a8[6] += qv * k1.z; a8[7] += qv * k1.w;
            if ((lid & 1) == 0) sq += qv * qv;
            if (c == 0) {
                sk8[0] += k0.x * k0.x; sk8[1] += k0.y * k0.y;
                sk8[2] += k0.z * k0.z; sk8[3] += k0.w * k0.w;
                sk8[4] += k1.x * k1.x; sk8[5] += k1.y * k1.y;
                sk8[6] += k1.z * k1.z; sk8[7] += k1.w * k1.w;
            }
        }
        const int bh = b * HEADS + h;
#pragma unroll
        for (int j = 0; j < 8; j++)
            atomicAdd(&G[(size_t)bh * 256 + c * 16 + d0 + j], a8[j]);
        if ((lid & 1) == 0) atomicAdd(&SQ[bh * 16 + c], sq);
        if (c == 0)
#pragma unroll
            for (int j = 0; j < 8; j++) atomicAdd(&SK[bh * 16 + d0 + j], sk8[j]);
    }
}

// ---------------- converters ----------------
__global__ void cvt_f16(const float* __restrict__ src, f16* __restrict__ dst, int n4) {
    int i = blockIdx.x * 256 + threadIdx.x;
    if (i >= n4) return;
    float4 v = ((const float4*)src)[i];
    f16 h[4] = {__float2half_rn(v.x), __float2half_rn(v.y),
                __float2half_rn(v.z), __float2half_rn(v.w)};
    ((uint2*)dst)[i] = *(uint2*)h;
}

__device__ __forceinline__ void split_store(const float4& v, f16* hi, f16* lo, int i) {
    float a[4] = {v.x, v.y, v.z, v.w};
    f16 h[4], l[4];
#pragma unroll
    for (int j = 0; j < 4; j++) {
        h[j] = __float2half_rn(a[j]);
        l[j] = __float2half_rn(a[j] - __half2float(h[j]));
    }
    ((uint2*)hi)[i] = *(uint2*)h;
    ((uint2*)lo)[i] = *(uint2*)l;
}

__global__ void cvt_split_h(const float* __restrict__ src, f16* __restrict__ hi,
                            f16* __restrict__ lo, int n4) {
    int i = blockIdx.x * 256 + threadIdx.x;
    if (i >= n4) return;
    split_store(((const float4*)src)[i], hi, lo, i);
}

// merged weight prep: y=0 -> w_qkv, y=1 -> w_q, y=2 -> w_k  (all 48K elems)
__global__ void prep_w(const float* __restrict__ wqkv, const float* __restrict__ wq,
                       const float* __restrict__ wk,
                       f16* __restrict__ qkvh, f16* __restrict__ qkvl,
                       f16* __restrict__ qh, f16* __restrict__ ql,
                       f16* __restrict__ kh, f16* __restrict__ kl, int n4) {
    int i = blockIdx.x * 256 + threadIdx.x;
    if (i >= n4) return;
    if (blockIdx.y == 0)      split_store(((const float4*)wqkv)[i], qkvh, qkvl, i);
    else if (blockIdx.y == 1) split_store(((const float4*)wq)[i], qh, ql, i);
    else                      split_store(((const float4*)wk)[i], kh, kl, i);
}

// ---------------- fused depthwise conv (fp16 in/out) ----------------
__global__ void __launch_bounds__(256)
dwconv_kernel(const f16* __restrict__ xq, const float* __restrict__ w3,
              const float* __restrict__ w5, const float* __restrict__ w7,
              f16* __restrict__ D) {
    __shared__ float tile[22][72];
    __shared__ float s3[9], s5[25], s7[49];

    const int bc = blockIdx.z;
    const int b = bc / C3, c = bc % C3;
    const int x0 = blockIdx.x * 64, y0 = blockIdx.y * 16;
    const int tid = threadIdx.x;

    const f16* src = xq + (size_t)bc * HWSZ;
    if (tid < 9) s3[tid] = w3[c * 9 + tid];
    if (tid < 25) s5[tid] = w5[c * 25 + tid];
    if (tid < 49) s7[tid] = w7[c * 49 + tid];

    for (int e = tid; e < 22 * 70; e += 256) {
        int iy = e / 70, ix = e % 70;
        int gy = y0 - 3 + iy, gx = x0 - 3 + ix;
        float v = 0.f;
        if (gy >= 0 && gy < IMG && gx >= 0 && gx < IMG) v = __half2float(src[gy * IMG + gx]);
        tile[iy][ix] = v;
    }
    __syncthreads();

    const int ty = tid >> 4, tx = (tid & 15) * 4;
    float a3[4] = {0, 0, 0, 0}, a5[4] = {0, 0, 0, 0}, a7[4] = {0, 0, 0, 0};
#pragma unroll
    for (int ky = 0; ky < 7; ky++) {
        float r[10];
#pragma unroll
        for (int j = 0; j < 10; j++) r[j] = tile[ty + ky][tx + j];
#pragma unroll
        for (int kx = 0; kx < 7; kx++) {
            float w = s7[ky * 7 + kx];
#pragma unroll
            for (int xi = 0; xi < 4; xi++) a7[xi] += r[kx + xi] * w;
        }
        if (ky >= 1 && ky <= 5) {
#pragma unroll
            for (int kx = 0; kx < 5; kx++) {
                float w = s5[(ky - 1) * 5 + kx];
#pragma unroll
                for (int xi = 0; xi < 4; xi++) a5[xi] += r[kx + 1 + xi] * w;
            }
        }
        if (ky >= 2 && ky <= 4) {
#pragma unroll
            for (int kx = 0; kx < 3; kx++) {
                float w = s3[(ky - 2) * 3 + kx];
#pragma unroll
                for (int xi = 0; xi < 4; xi++) a3[xi] += r[kx + 2 + xi] * w;
            }
        }
    }

    size_t o = ((size_t)b * 3 * C3 + c) * HWSZ + (size_t)(y0 + ty) * IMG + (x0 + tx);
    f16 h3[4] = {__float2half_rn(a3[0]), __float2half_rn(a3[1]),
                 __float2half_rn(a3[2]), __float2half_rn(a3[3])};
    f16 h5[4] = {__float2half_rn(a5[0]), __float2half_rn(a5[1]),
                 __float2half_rn(a5[2]), __float2half_rn(a5[3])};
    f16 h7[4] = {__float2half_rn(a7[0]), __float2half_rn(a7[1]),
                 __float2half_rn(a7[2]), __float2half_rn(a7[3])};
    *(uint2*)&D[o] = *(uint2*)h3;
    *(uint2*)&D[o + (size_t)C3 * HWSZ] = *(uint2*)h5;
    *(uint2*)&D[o + (size_t)2 * C3 * HWSZ] = *(uint2*)h7;
}

// ---------------- softmax finalize ----------------
__global__ void attn_finalize(const float* __restrict__ G, const float* __restrict__ SQ,
                              const float* __restrict__ SK, const float* __restrict__ temp,
                              float* __restrict__ attn) {
    const int bh = blockIdx.x, h = bh & 7, c = threadIdx.x;
    if (c >= 16) return;
    float nq = fmaxf(sqrtf(SQ[bh * 16 + c]), 1e-12f);
    float t = temp[h];
    float s[16], mx = -1e30f;
#pragma unroll
    for (int d = 0; d < 16; d++) {
        float nk = fmaxf(sqrtf(SK[bh * 16 + d]), 1e-12f);
        s[d] = G[bh * 256 + c * 16 + d] / (nq * nk) * t;
        mx = fmaxf(mx, s[d]);
    }
    float sum = 0.f;
#pragma unroll
    for (int d = 0; d < 16; d++) { s[d] = expf(s[d] - mx); sum += s[d]; }
    float inv = 1.f / sum;
#pragma unroll
    for (int d = 0; d < 16; d++) attn[bh * 256 + c * 16 + d] = s[d] * inv;
}

// ---------------- T1 / M ----------------
__global__ void t1_kernel(const float* __restrict__ attn, const float* __restrict__ wv,
                          float* __restrict__ T1) {
    const int bm = blockIdx.x, b = bm >> 7, m = bm & 127, h = m >> 4, cm = m & 15;
    __shared__ float a[16];
    if (threadIdx.x < 16) a[threadIdx.x] = attn[((b * 8 + h) * 16 + cm) * 16 + threadIdx.x];
    __syncthreads();
    const int r = threadIdx.x;
    float acc = 0.f;
#pragma unroll
    for (int d = 0; d < 16; d++) acc += a[d] * wv[(h * 16 + d) * C3 + r];
    T1[((size_t)b * CB + m) * C3 + r] = acc;
}

__global__ void m_kernel(const float* __restrict__ wout, const float* __restrict__ T1,
                         float* __restrict__ Mo) {
    const int bo = blockIdx.x, b = bo >> 7, o = bo & 127;
    __shared__ float w[128];
    if (threadIdx.x < 128) w[threadIdx.x] = wout[o * 128 + threadIdx.x];
    __syncthreads();
    const int r = threadIdx.x;
    float acc = 0.f;
#pragma unroll 8
    for (int m = 0; m < 128; m++) acc += w[m] * T1[((size_t)b * CB + m) * C3 + r];
    Mo[((size_t)b * CB + o) * C3 + r] = acc;
}

__global__ void zero_stats(float* __restrict__ G, float* __restrict__ SQ,
                           float* __restrict__ SK) {
    int i = blockIdx.x * 256 + threadIdx.x;
    if (i < BATCH * HEADS * 256) G[i] = 0.f;
    if (i < BATCH * HEADS * 16) { SQ[i] = 0.f; SK[i] = 0.f; }
}

// ---------------- host launcher ----------------
extern "C" void kernel_launch(void* const* d_in, const int* in_sizes, int n_in,
                              void* d_out, int out_size) {
    const float* x     = (const float*)d_in[0];
    const float* w_qkv = (const float*)d_in[1];
    const float* w_dw3 = (const float*)d_in[2];
    const float* w_dw5 = (const float*)d_in[3];
    const float* w_dw7 = (const float*)d_in[4];
    const float* w_q   = (const float*)d_in[5];
    const float* w_k   = (const float*)d_in[6];
    const float* w_v   = (const float*)d_in[7];
    const float* w_out = (const float*)d_in[8];
    const float* temp  = (const float*)d_in[9];
    float* out = (float*)d_out;

    float *p_gram, *p_ssq, *p_ssk, *p_attn, *p_T1, *p_M;
    f16 *p_x16, *p_xq16, *p_D16, *p_wqkvh, *p_wqkvl, *p_wqh, *p_wql, *p_wkh, *p_wkl, *p_Mh, *p_Ml;
    cudaGetSymbolAddress((void**)&p_x16, g_x16);
    cudaGetSymbolAddress((void**)&p_xq16, g_xq16);
    cudaGetSymbolAddress((void**)&p_D16, g_D16);
    cudaGetSymbolAddress((void**)&p_gram, g_gram);
    cudaGetSymbolAddress((void**)&p_ssq, g_ssq);
    cudaGetSymbolAddress((void**)&p_ssk, g_ssk);
    cudaGetSymbolAddress((void**)&p_attn, g_attn);
    cudaGetSymbolAddress((void**)&p_T1, g_T1);
    cudaGetSymbolAddress((void**)&p_M, g_M);
    cudaGetSymbolAddress((void**)&p_wqkvh, g_wqkv_h);
    cudaGetSymbolAddress((void**)&p_wqkvl, g_wqkv_l);
    cudaGetSymbolAddress((void**)&p_wqh, g_wq_h);
    cudaGetSymbolAddress((void**)&p_wql, g_wq_l);
    cudaGetSymbolAddress((void**)&p_wkh, g_wk_h);
    cudaGetSymbolAddress((void**)&p_wkl, g_wk_l);
    cudaGetSymbolAddress((void**)&p_Mh, g_Mh);
    cudaGetSymbolAddress((void**)&p_Ml, g_Ml);

    cudaFuncSetAttribute(tc_gemm_f32, cudaFuncAttributeMaxDynamicSharedMemorySize, STG_BYTES);
    cudaFuncSetAttribute(tc_gemm_f16, cudaFuncAttributeMaxDynamicSharedMemorySize, STG_BYTES);
    cudaFuncSetAttribute(qk_gram, cudaFuncAttributeMaxDynamicSharedMemorySize, QKG_BYTES);

    // harness issues 2 pre-launches; ncu -s 5 captures OUR launch idx 3 -> gemm1.
    zero_stats<<<64, 256>>>(p_gram, p_ssq, p_ssk);                              // 0
    {
        int n4 = BATCH * CB * HWSZ / 4;
        cvt_f16<<<(n4 + 255) / 256, 256>>>(x, p_x16, n4);                       // 1
    }
    prep_w<<<dim3(48, 3), 256>>>(w_qkv, w_q, w_k, p_wqkvh, p_wqkvl,
                                 p_wqh, p_wql, p_wkh, p_wkl, C3 * CB / 4);      // 2

    // 1) xq = w_qkv @ x  (M=384, K=128) -> fp16      [profiled launch]
    tc_gemm_f16<<<dim3(3, 128, BATCH), 256, STG_BYTES>>>(                       // 3
        p_wqkvh, p_wqkvl, 128, (size_t)0,
        p_x16, (size_t)CB * HWSZ, (size_t)CB * HWSZ,
        p_xq16, (size_t)C3 * HWSZ);

    // 2) depthwise conv -> D fp16
    dwconv_kernel<<<dim3(2, 8, BATCH * C3), 256>>>(p_xq16, w_dw3, w_dw5, w_dw7, p_D16);

    // 3) fused q/k projections + gram + sumsq
    qk_gram<<<dim3(128, BATCH), 256, QKG_BYTES>>>(
        p_wqh, p_wql, p_wkh, p_wkl, p_D16, p_gram, p_ssq, p_ssk);

    attn_finalize<<<BATCH * HEADS, 32>>>(p_gram, p_ssq, p_ssk, temp, p_attn);

    // 4) M_b = w_out @ blockdiag(attn) @ w_v -> fp16 split
    t1_kernel<<<BATCH * CB, 384>>>(p_attn, w_v, p_T1);
    m_kernel<<<BATCH * CB, 384>>>(w_out, p_T1, p_M);
    cvt_split_h<<<384, 256>>>(p_M, p_Mh, p_Ml, BATCH * CB * C3 / 4);

    // 5) out = M_b @ D(v-part)  (M=128, K=384)
    tc_gemm_f32<<<dim3(1, 128, BATCH), 256, STG_BYTES>>>(
        p_Mh, p_Ml, 384, (size_t)CB * C3,
        p_D16 + (size_t)2 * CB * HWSZ, (size_t)3 * C3 * HWSZ, (size_t)C3 * HWSZ,
        out, (size_t)CB * HWSZ);
}

// round 10
// speedup vs baseline: 2.4611x; 1.0152x over previous
#include <cuda_runtime.h>
#include <cuda_fp16.h>
#include <cstddef>
#include <cstdint>
#include <math.h>

#define HWSZ 16384
#define IMG 128
#define CB 128
#define C3 384
#define BATCH 8
#define HEADS 8
#define KCH 32

typedef __half f16;

// smem: A [2buf][2pl][128][40] f16, B [2buf][32][136] f16
#define SA_ROW 40
#define SB_ROW 136
#define SA_PLANE (128 * SA_ROW)          // 5120
#define SB_PLANE (32 * SB_ROW)           // 4352
#define SA_ELEMS (4 * SA_PLANE)          // 20480
#define SB_ELEMS (2 * SB_PLANE)          // 8704
#define STG_H (SA_ELEMS + SB_ELEMS)      // 29184 halves
#define STG_BYTES (STG_H * 2)            // 58368
// qk_gram: kst (fp16, 128x136) overlaps staging; qst (fp16) after staging
#define QST_H (128 * 136)                // 17408 halves = 34816 B
#define QKG_BYTES ((STG_H + QST_H) * 2)  // 93184 B -> 2 CTAs/SM

// ---------------- scratch ----------------
__device__ __align__(128) f16 g_xq16[(size_t)BATCH * C3 * HWSZ];
__device__ __align__(128) f16 g_D16[(size_t)BATCH * 3 * C3 * HWSZ];
__device__ __align__(128) f16 g_wqkv_h[C3 * CB], g_wqkv_l[C3 * CB];
__device__ __align__(128) f16 g_wq_h[CB * C3], g_wq_l[CB * C3];
__device__ __align__(128) f16 g_wk_h[CB * C3], g_wk_l[CB * C3];
__device__ __align__(128) f16 g_Mh[BATCH * CB * C3], g_Ml[BATCH * CB * C3];
__device__ float g_gram[BATCH * HEADS * 256];
__device__ float g_ssq[BATCH * HEADS * 16];
__device__ float g_ssk[BATCH * HEADS * 16];
__device__ float g_attn[BATCH * HEADS * 256];
__device__ float g_T1[BATCH * CB * C3];
__device__ float g_M[BATCH * CB * C3];

// ---------------- helpers ----------------
__device__ __forceinline__ uint32_t smem_u32(const void* p) {
    uint32_t a;
    asm("{ .reg .u64 t; cvta.to.shared.u64 t, %1; cvt.u32.u64 %0, t; }" : "=r"(a) : "l"(p));
    return a;
}
__device__ __forceinline__ void ldm_x4(uint32_t* r, uint32_t addr) {
    asm volatile("ldmatrix.sync.aligned.m8n8.x4.shared.b16 {%0,%1,%2,%3}, [%4];"
                 : "=r"(r[0]), "=r"(r[1]), "=r"(r[2]), "=r"(r[3]) : "r"(addr));
}
__device__ __forceinline__ void ldm_x2t(uint32_t* r, uint32_t addr) {
    asm volatile("ldmatrix.sync.aligned.m8n8.x2.trans.shared.b16 {%0,%1}, [%2];"
                 : "=r"(r[0]), "=r"(r[1]) : "r"(addr));
}
__device__ __forceinline__ void mma16816(float* d, const uint32_t* a, const uint32_t* b) {
    asm volatile(
        "mma.sync.aligned.m16n8k16.row.col.f32.f16.f16.f32 "
        "{%0,%1,%2,%3}, {%4,%5,%6,%7}, {%8,%9}, {%0,%1,%2,%3};"
        : "+f"(d[0]), "+f"(d[1]), "+f"(d[2]), "+f"(d[3])
        : "r"(a[0]), "r"(a[1]), "r"(a[2]), "r"(a[3]), "r"(b[0]), "r"(b[1]));
}
// load 8 fp32 from global, convert -> 8 halves packed in uint4
__device__ __forceinline__ uint4 load8f_cvt(const float* p) {
    float4 a = *(const float4*)p;
    float4 b = *(const float4*)(p + 4);
    f16 h[8] = {__float2half_rn(a.x), __float2half_rn(a.y), __float2half_rn(a.z),
                __float2half_rn(a.w), __float2half_rn(b.x), __float2half_rn(b.y),
                __float2half_rn(b.z), __float2half_rn(b.w)};
    return *(uint4*)h;
}

// ---- HMMA mainloop: acc += (Ah+Al)·B, 128m x 128n tile, fp16 2-term ----
// A row-major [.][Ktot] (hi/lo planes); B row r at B + (r>>7)*sStr + (r&127)*HWSZ, +n0.
// BF32: B source is fp32 (converted to fp16 during staging).
template <bool BF32>
__device__ __forceinline__ void gemm_mainloop(
    const f16* __restrict__ Ahb, const f16* __restrict__ Alb, int Ktot, int m0,
    const void* __restrict__ Bb, size_t sStr, int n0,
    f16* sA, f16* sB, int tid, int wid, int lid, float acc[4][4][4]) {
    const int wm = (wid >> 2) * 64, wn = (wid & 3) * 32;
    const int nchunks = Ktot / KCH;
    const f16* B16 = (const f16*)Bb;
    const float* B32 = (const float*)Bb;

    // stage chunk 0 into buf 0
#pragma unroll
    for (int i = 0; i < 4; i++) {
        int u = tid + i * 256;
        int pl = u >> 9, v = u & 511;
        int m = v >> 2, kq = v & 3;
        const f16* src = (pl ? Alb : Ahb) + (size_t)(m0 + m) * Ktot + kq * 8;
        *(uint4*)(sA + pl * SA_PLANE + m * SA_ROW + kq * 8) = *(const uint4*)src;
    }
#pragma unroll
    for (int i = 0; i < 2; i++) {
        int u = tid + i * 256;
        int k = u >> 4, nu = u & 15;
        size_t off = (size_t)(k >> 7) * sStr + (size_t)(k & 127) * HWSZ + n0 + nu * 8;
        uint4 val;
        if (BF32) val = load8f_cvt(B32 + off);
        else      val = *(const uint4*)(B16 + off);
        *(uint4*)(sB + k * SB_ROW + nu * 8) = val;
    }
    __syncthreads();

    int buf = 0;
#pragma unroll 1
    for (int ch = 0; ch < nchunks; ch++) {
        const bool more = (ch + 1) < nchunks;
        uint4 pa[4], pb[2];
        if (more) {
            const int k0 = (ch + 1) * KCH;
#pragma unroll
            for (int i = 0; i < 4; i++) {
                int u = tid + i * 256;
                int pl = u >> 9, v = u & 511;
                int m = v >> 2, kq = v & 3;
                pa[i] = *(const uint4*)((pl ? Alb : Ahb) + (size_t)(m0 + m) * Ktot + k0 + kq * 8);
            }
#pragma unroll
            for (int i = 0; i < 2; i++) {
                int u = tid + i * 256;
                int k = u >> 4, nu = u & 15;
                int r = k0 + k;
                size_t off = (size_t)(r >> 7) * sStr + (size_t)(r & 127) * HWSZ + n0 + nu * 8;
                if (BF32) pb[i] = load8f_cvt(B32 + off);
                else      pb[i] = *(const uint4*)(B16 + off);
            }
        }

        const uint32_t aBase0 = smem_u32(sA + (buf * 2 + 0) * SA_PLANE);
        const uint32_t aBase1 = smem_u32(sA + (buf * 2 + 1) * SA_PLANE);
        const uint32_t bBase = smem_u32(sB + buf * SB_PLANE);
#pragma unroll
        for (int k16 = 0; k16 < 2; k16++) {
            const int kk = k16 * 16;
            uint32_t aF[2][4][4], bF[4][2];
            const uint32_t aOff =
                ((uint32_t)((wm + (lid & 15)) * SA_ROW + kk + ((lid >> 4) << 3))) * 2;
#pragma unroll
            for (int mb = 0; mb < 4; mb++) {
                ldm_x4(aF[0][mb], aBase0 + aOff + mb * 16 * SA_ROW * 2);
                ldm_x4(aF[1][mb], aBase1 + aOff + mb * 16 * SA_ROW * 2);
            }
            const uint32_t bOff = ((uint32_t)((kk + (lid & 15)) * SB_ROW + wn)) * 2;
#pragma unroll
            for (int nb = 0; nb < 4; nb++) ldm_x2t(bF[nb], bBase + bOff + nb * 16);
#pragma unroll
            for (int mb = 0; mb < 4; mb++)
#pragma unroll
                for (int nb = 0; nb < 4; nb++) {
                    mma16816(acc[mb][nb], aF[0][mb], bF[nb]);
                    mma16816(acc[mb][nb], aF[1][mb], bF[nb]);
                }
        }
        __syncthreads();

        if (more) {
            const int nb2 = buf ^ 1;
#pragma unroll
            for (int i = 0; i < 4; i++) {
                int u = tid + i * 256;
                int pl = u >> 9, v = u & 511;
                int m = v >> 2, kq = v & 3;
                *(uint4*)(sA + (nb2 * 2 + pl) * SA_PLANE + m * SA_ROW + kq * 8) = pa[i];
            }
#pragma unroll
            for (int i = 0; i < 2; i++) {
                int u = tid + i * 256;
                int k = u >> 4, nu = u & 15;
                *(uint4*)(sB + nb2 * SB_PLANE + k * SB_ROW + nu * 8) = pb[i];
            }
            __syncthreads();
            buf = nb2;
        }
    }
}

// ================= GEMM, fp32 output (out-gemm) =================
__global__ void __launch_bounds__(256, 2)
tc_gemm_f32(const f16* __restrict__ Ah, const f16* __restrict__ Al, int Ktot, size_t aStr,
            const f16* __restrict__ B, size_t bStr, size_t sStr,
            float* __restrict__ C, size_t cStr) {
    extern __shared__ f16 dsm[];
    f16* sA = dsm;
    f16* sB = dsm + SA_ELEMS;
    const int tid = threadIdx.x, wid = tid >> 5, lid = tid & 31;
    const int m0 = blockIdx.x * 128, n0 = blockIdx.y * 128, b = blockIdx.z;
    const int wm = (wid >> 2) * 64, wn = (wid & 3) * 32;

    float acc[4][4][4];
#pragma unroll
    for (int i = 0; i < 4; i++)
#pragma unroll
        for (int j = 0; j < 4; j++)
#pragma unroll
            for (int t = 0; t < 4; t++) acc[i][j][t] = 0.f;

    gemm_mainloop<false>(Ah + (size_t)b * aStr, Al + (size_t)b * aStr, Ktot, m0,
                         B + (size_t)b * bStr, sStr, n0, sA, sB, tid, wid, lid, acc);

    float* Cp = C + (size_t)b * cStr;
    const int g = lid >> 2, t = lid & 3;
#pragma unroll
    for (int mb = 0; mb < 4; mb++)
#pragma unroll
        for (int nb = 0; nb < 4; nb++) {
            int m = m0 + wm + mb * 16 + g;
            int n = n0 + wn + nb * 8 + t * 2;
            *(float2*)&Cp[(size_t)m * HWSZ + n] = make_float2(acc[mb][nb][0], acc[mb][nb][1]);
            *(float2*)&Cp[(size_t)(m + 8) * HWSZ + n] = make_float2(acc[mb][nb][2], acc[mb][nb][3]);
        }
}

// ================= GEMM, fp16 output (gemm1: B read from fp32 x) ==========
__global__ void __launch_bounds__(256, 2)
tc_gemm_f16_bf32(const f16* __restrict__ Ah, const f16* __restrict__ Al, int Ktot, size_t aStr,
                 const float* __restrict__ B, size_t bStr, size_t sStr,
                 f16* __restrict__ C, size_t cStr) {
    extern __shared__ f16 dsm[];
    f16* sA = dsm;
    f16* sB = dsm + SA_ELEMS;
    const int tid = threadIdx.x, wid = tid >> 5, lid = tid & 31;
    const int m0 = blockIdx.x * 128, n0 = blockIdx.y * 128, b = blockIdx.z;
    const int wm = (wid >> 2) * 64, wn = (wid & 3) * 32;

    float acc[4][4][4];
#pragma unroll
    for (int i = 0; i < 4; i++)
#pragma unroll
        for (int j = 0; j < 4; j++)
#pragma unroll
            for (int t = 0; t < 4; t++) acc[i][j][t] = 0.f;

    gemm_mainloop<true>(Ah + (size_t)b * aStr, Al + (size_t)b * aStr, Ktot, m0,
                        B + (size_t)b * bStr, sStr, n0, sA, sB, tid, wid, lid, acc);

    f16* Cp = C + (size_t)b * cStr;
    const int g = lid >> 2, t = lid & 3;
#pragma unroll
    for (int mb = 0; mb < 4; mb++)
#pragma unroll
        for (int nb = 0; nb < 4; nb++) {
            int m = m0 + wm + mb * 16 + g;
            int n = n0 + wn + nb * 8 + t * 2;
            __half2 v01 = __floats2half2_rn(acc[mb][nb][0], acc[mb][nb][1]);
            __half2 v23 = __floats2half2_rn(acc[mb][nb][2], acc[mb][nb][3]);
            *(__half2*)&Cp[(size_t)m * HWSZ + n] = v01;
            *(__half2*)&Cp[(size_t)(m + 8) * HWSZ + n] = v23;
        }
}

// ====== fused q-proj + k-proj + per-head gram/sumsq (fp16 q/k tiles) ======
__global__ void __launch_bounds__(256, 2)
qk_gram(const f16* __restrict__ wqh, const f16* __restrict__ wql,
        const f16* __restrict__ wkh, const f16* __restrict__ wkl,
        const f16* __restrict__ D,
        float* __restrict__ G, float* __restrict__ SQ, float* __restrict__ SK) {
    extern __shared__ f16 dsm[];
    f16* sA = dsm;
    f16* sB = dsm + SA_ELEMS;
    f16* qsth = dsm + STG_H;   // [128 n][136] transposed q, fp16
    f16* ksth = dsm;           // overlaps staging (written after phase B)

    const int tid = threadIdx.x, wid = tid >> 5, lid = tid & 31;
    const int n0 = blockIdx.x * 128, b = blockIdx.y;
    const int wm = (wid >> 2) * 64, wn = (wid & 3) * 32;
    const int g = lid >> 2, t4 = lid & 3;

    const f16* Db = D + (size_t)b * 3 * C3 * HWSZ;

    float acc[4][4][4];
#pragma unroll
    for (int i = 0; i < 4; i++)
#pragma unroll
        for (int j = 0; j < 4; j++)
#pragma unroll
            for (int t = 0; t < 4; t++) acc[i][j][t] = 0.f;

    // ---- phase A: q tile ----
    gemm_mainloop<false>(wqh, wql, C3, 0, Db, (size_t)C3 * HWSZ, n0,
                         sA, sB, tid, wid, lid, acc);
#pragma unroll
    for (int mb = 0; mb < 4; mb++)
#pragma unroll
        for (int nb = 0; nb < 4; nb++) {
            int m = wm + mb * 16 + g;
            int n = wn + nb * 8 + t4 * 2;
            qsth[n * 136 + m] = __float2half_rn(acc[mb][nb][0]);
            qsth[(n + 1) * 136 + m] = __float2half_rn(acc[mb][nb][1]);
            qsth[n * 136 + m + 8] = __float2half_rn(acc[mb][nb][2]);
            qsth[(n + 1) * 136 + m + 8] = __float2half_rn(acc[mb][nb][3]);
            acc[mb][nb][0] = acc[mb][nb][1] = acc[mb][nb][2] = acc[mb][nb][3] = 0.f;
        }
    __syncthreads();

    // ---- phase B: k tile ----
    gemm_mainloop<false>(wkh, wkl, C3, 0, Db + (size_t)CB * HWSZ, (size_t)C3 * HWSZ, n0,
                         sA, sB, tid, wid, lid, acc);
    __syncthreads();   // staging reads done before kst overwrite
#pragma unroll
    for (int mb = 0; mb < 4; mb++)
#pragma unroll
        for (int nb = 0; nb < 4; nb++) {
            int m = wm + mb * 16 + g;
            int n = wn + nb * 8 + t4 * 2;
            ksth[n * 136 + m] = __float2half_rn(acc[mb][nb][0]);
            ksth[(n + 1) * 136 + m] = __float2half_rn(acc[mb][nb][1]);
            ksth[n * 136 + m + 8] = __float2half_rn(acc[mb][nb][2]);
            ksth[(n + 1) * 136 + m + 8] = __float2half_rn(acc[mb][nb][3]);
        }
    __syncthreads();

    // ---- phase C: per-head gram + sumsq ----
    {
        const int h = wid;                // 8 warps = 8 heads
        const int c = lid >> 1;           // 0..15
        const int d0 = (lid & 1) * 8;     // 0 or 8
        float a8[8] = {0, 0, 0, 0, 0, 0, 0, 0};
        float sq = 0.f, sk8[8] = {0, 0, 0, 0, 0, 0, 0, 0};
#pragma unroll 4
        for (int n = 0; n < 128; n++) {
            float qv = __half2float(qsth[n * 136 + h * 16 + c]);
            uint4 kvu = *(const uint4*)&ksth[n * 136 + h * 16 + d0];
            __half2* kh2 = (__half2*)&kvu;
            float2 k01 = __half22float2(kh2[0]);
            float2 k23 = __half22float2(kh2[1]);
            float2 k45 = __half22float2(kh2[2]);
            float2 k67 = __half22float2(kh2[3]);
            a8[0] += qv * k01.x; a8[1] += qv * k01.y;
            a8[2] += qv * k23.x; a8[3] += qv * k23.y;
            a8[4] += qv * k45.x; a8[5] += qv * k45.y;
            a8[6] += qv * k67.x; a8[7] += qv * k67.y;
            if ((lid & 1) == 0) sq += qv * qv;
            if (c == 0) {
                sk8[0] += k01.x * k01.x; sk8[1] += k01.y * k01.y;
                sk8[2] += k23.x * k23.x; sk8[3] += k23.y * k23.y;
                sk8[4] += k45.x * k45.x; sk8[5] += k45.y * k45.y;
                sk8[6] += k67.x * k67.x; sk8[7] += k67.y * k67.y;
            }
        }
        const int bh = b * HEADS + h;
#pragma unroll
        for (int j = 0; j < 8; j++)
            atomicAdd(&G[(size_t)bh * 256 + c * 16 + d0 + j], a8[j]);
        if ((lid & 1) == 0) atomicAdd(&SQ[bh * 16 + c], sq);
        if (c == 0)
#pragma unroll
            for (int j = 0; j < 8; j++) atomicAdd(&SK[bh * 16 + d0 + j], sk8[j]);
    }
}

// ---------------- prep: zero stats + split all 3 weight matrices ----------
__device__ __forceinline__ void split_store(const float4& v, f16* hi, f16* lo, int i) {
    float a[4] = {v.x, v.y, v.z, v.w};
    f16 h[4], l[4];
#pragma unroll
    for (int j = 0; j < 4; j++) {
        h[j] = __float2half_rn(a[j]);
        l[j] = __float2half_rn(a[j] - __half2float(h[j]));
    }
    ((uint2*)hi)[i] = *(uint2*)h;
    ((uint2*)lo)[i] = *(uint2*)l;
}

__global__ void prep_all(const float* __restrict__ wqkv, const float* __restrict__ wq,
                         const float* __restrict__ wk,
                         f16* __restrict__ qkvh, f16* __restrict__ qkvl,
                         f16* __restrict__ qh, f16* __restrict__ ql,
                         f16* __restrict__ kh, f16* __restrict__ kl,
                         float* __restrict__ G, float* __restrict__ SQ,
                         float* __restrict__ SK) {
    int i = blockIdx.x * 256 + threadIdx.x;
    int y = blockIdx.y;
    const int n4 = C3 * CB / 4;   // 12288
    if (y == 0) {
        if (i < n4) split_store(((const float4*)wqkv)[i], qkvh, qkvl, i);
    } else if (y == 1) {
        if (i < n4) split_store(((const float4*)wq)[i], qh, ql, i);
    } else if (y == 2) {
        if (i < n4) split_store(((const float4*)wk)[i], kh, kl, i);
    } else {
        if (i < BATCH * HEADS * 256) G[i] = 0.f;
        if (i < BATCH * HEADS * 16) { SQ[i] = 0.f; SK[i] = 0.f; }
    }
}

__global__ void cvt_split_h(const float* __restrict__ src, f16* __restrict__ hi,
                            f16* __restrict__ lo, int n4) {
    int i = blockIdx.x * 256 + threadIdx.x;
    if (i >= n4) return;
    split_store(((const float4*)src)[i], hi, lo, i);
}

// ---------------- fused depthwise conv (fp16 in/out) ----------------
__global__ void __launch_bounds__(256)
dwconv_kernel(const f16* __restrict__ xq, const float* __restrict__ w3,
              const float* __restrict__ w5, const float* __restrict__ w7,
              f16* __restrict__ D) {
    __shared__ float tile[22][72];
    __shared__ float s3[9], s5[25], s7[49];

    const int bc = blockIdx.z;
    const int b = bc / C3, c = bc % C3;
    const int x0 = blockIdx.x * 64, y0 = blockIdx.y * 16;
    const int tid = threadIdx.x;

    const f16* src = xq + (size_t)bc * HWSZ;
    if (tid < 9) s3[tid] = w3[c * 9 + tid];
    if (tid < 25) s5[tid] = w5[c * 25 + tid];
    if (tid < 49) s7[tid] = w7[c * 49 + tid];

    for (int e = tid; e < 22 * 70; e += 256) {
        int iy = e / 70, ix = e % 70;
        int gy = y0 - 3 + iy, gx = x0 - 3 + ix;
        float v = 0.f;
        if (gy >= 0 && gy < IMG && gx >= 0 && gx < IMG) v = __half2float(src[gy * IMG + gx]);
        tile[iy][ix] = v;
    }
    __syncthreads();

    const int ty = tid >> 4, tx = (tid & 15) * 4;
    float a3[4] = {0, 0, 0, 0}, a5[4] = {0, 0, 0, 0}, a7[4] = {0, 0, 0, 0};
#pragma unroll
    for (int ky = 0; ky < 7; ky++) {
        float r[10];
#pragma unroll
        for (int j = 0; j < 10; j++) r[j] = tile[ty + ky][tx + j];
#pragma unroll
        for (int kx = 0; kx < 7; kx++) {
            float w = s7[ky * 7 + kx];
#pragma unroll
            for (int xi = 0; xi < 4; xi++) a7[xi] += r[kx + xi] * w;
        }
        if (ky >= 1 && ky <= 5) {
#pragma unroll
            for (int kx = 0; kx < 5; kx++) {
                float w = s5[(ky - 1) * 5 + kx];
#pragma unroll
                for (int xi = 0; xi < 4; xi++) a5[xi] += r[kx + 1 + xi] * w;
            }
        }
        if (ky >= 2 && ky <= 4) {
#pragma unroll
            for (int kx = 0; kx < 3; kx++) {
                float w = s3[(ky - 2) * 3 + kx];
#pragma unroll
                for (int xi = 0; xi < 4; xi++) a3[xi] += r[kx + 2 + xi] * w;
            }
        }
    }

    size_t o = ((size_t)b * 3 * C3 + c) * HWSZ + (size_t)(y0 + ty) * IMG + (x0 + tx);
    f16 h3[4] = {__float2half_rn(a3[0]), __float2half_rn(a3[1]),
                 __float2half_rn(a3[2]), __float2half_rn(a3[3])};
    f16 h5[4] = {__float2half_rn(a5[0]), __float2half_rn(a5[1]),
                 __float2half_rn(a5[2]), __float2half_rn(a5[3])};
    f16 h7[4] = {__float2half_rn(a7[0]), __float2half_rn(a7[1]),
                 __float2half_rn(a7[2]), __float2half_rn(a7[3])};
    *(uint2*)&D[o] = *(uint2*)h3;
    *(uint2*)&D[o + (size_t)C3 * HWSZ] = *(uint2*)h5;
    *(uint2*)&D[o + (size_t)2 * C3 * HWSZ] = *(uint2*)h7;
}

// ---------------- softmax finalize ----------------
__global__ void attn_finalize(const float* __restrict__ G, const float* __restrict__ SQ,
                              const float* __restrict__ SK, const float* __restrict__ temp,
                              float* __restrict__ attn) {
    const int bh = blockIdx.x, h = bh & 7, c = threadIdx.x;
    if (c >= 16) return;
    float nq = fmaxf(sqrtf(SQ[bh * 16 + c]), 1e-12f);
    float t = temp[h];
    float s[16], mx = -1e30f;
#pragma unroll
    for (int d = 0; d < 16; d++) {
        float nk = fmaxf(sqrtf(SK[bh * 16 + d]), 1e-12f);
        s[d] = G[bh * 256 + c * 16 + d] / (nq * nk) * t;
        mx = fmaxf(mx, s[d]);
    }
    float sum = 0.f;
#pragma unroll
    for (int d = 0; d < 16; d++) { s[d] = expf(s[d] - mx); sum += s[d]; }
    float inv = 1.f / sum;
#pragma unroll
    for (int d = 0; d < 16; d++) attn[bh * 256 + c * 16 + d] = s[d] * inv;
}

// ---------------- T1 / M ----------------
__global__ void t1_kernel(const float* __restrict__ attn, const float* __restrict__ wv,
                          float* __restrict__ T1) {
    const int bm = blockIdx.x, b = bm >> 7, m = bm & 127, h = m >> 4, cm = m & 15;
    __shared__ float a[16];
    if (threadIdx.x < 16) a[threadIdx.x] = attn[((b * 8 + h) * 16 + cm) * 16 + threadIdx.x];
    __syncthreads();
    const int r = threadIdx.x;
    float acc = 0.f;
#pragma unroll
    for (int d = 0; d < 16; d++) acc += a[d] * wv[(h * 16 + d) * C3 + r];
    T1[((size_t)b * CB + m) * C3 + r] = acc;
}

__global__ void m_kernel(const float* __restrict__ wout, const float* __restrict__ T1,
                         float* __restrict__ Mo) {
    const int bo = blockIdx.x, b = bo >> 7, o = bo & 127;
    __shared__ float w[128];
    if (threadIdx.x < 128) w[threadIdx.x] = wout[o * 128 + threadIdx.x];
    __syncthreads();
    const int r = threadIdx.x;
    float acc = 0.f;
#pragma unroll 8
    for (int m = 0; m < 128; m++) acc += w[m] * T1[((size_t)b * CB + m) * C3 + r];
    Mo[((size_t)b * CB + o) * C3 + r] = acc;
}

// ---------------- host launcher ----------------
extern "C" void kernel_launch(void* const* d_in, const int* in_sizes, int n_in,
                              void* d_out, int out_size) {
    const float* x     = (const float*)d_in[0];
    const float* w_qkv = (const float*)d_in[1];
    const float* w_dw3 = (const float*)d_in[2];
    const float* w_dw5 = (const float*)d_in[3];
    const float* w_dw7 = (const float*)d_in[4];
    const float* w_q   = (const float*)d_in[5];
    const float* w_k   = (const float*)d_in[6];
    const float* w_v   = (const float*)d_in[7];
    const float* w_out = (const float*)d_in[8];
    const float* temp  = (const float*)d_in[9];
    float* out = (float*)d_out;

    float *p_gram, *p_ssq, *p_ssk, *p_attn, *p_T1, *p_M;
    f16 *p_xq16, *p_D16, *p_wqkvh, *p_wqkvl, *p_wqh, *p_wql, *p_wkh, *p_wkl, *p_Mh, *p_Ml;
    cudaGetSymbolAddress((void**)&p_xq16, g_xq16);
    cudaGetSymbolAddress((void**)&p_D16, g_D16);
    cudaGetSymbolAddress((void**)&p_gram, g_gram);
    cudaGetSymbolAddress((void**)&p_ssq, g_ssq);
    cudaGetSymbolAddress((void**)&p_ssk, g_ssk);
    cudaGetSymbolAddress((void**)&p_attn, g_attn);
    cudaGetSymbolAddress((void**)&p_T1, g_T1);
    cudaGetSymbolAddress((void**)&p_M, g_M);
    cudaGetSymbolAddress((void**)&p_wqkvh, g_wqkv_h);
    cudaGetSymbolAddress((void**)&p_wqkvl, g_wqkv_l);
    cudaGetSymbolAddress((void**)&p_wqh, g_wq_h);
    cudaGetSymbolAddress((void**)&p_wql, g_wq_l);
    cudaGetSymbolAddress((void**)&p_wkh, g_wk_h);
    cudaGetSymbolAddress((void**)&p_wkl, g_wk_l);
    cudaGetSymbolAddress((void**)&p_Mh, g_Mh);
    cudaGetSymbolAddress((void**)&p_Ml, g_Ml);

    cudaFuncSetAttribute(tc_gemm_f32, cudaFuncAttributeMaxDynamicSharedMemorySize, STG_BYTES);
    cudaFuncSetAttribute(tc_gemm_f16_bf32, cudaFuncAttributeMaxDynamicSharedMemorySize, STG_BYTES);
    cudaFuncSetAttribute(qk_gram, cudaFuncAttributeMaxDynamicSharedMemorySize, QKG_BYTES);

    // harness issues 2 pre-launches; ncu -s 5 captures OUR launch idx 3 -> qk_gram.
    prep_all<<<dim3(64, 4), 256>>>(w_qkv, w_q, w_k, p_wqkvh, p_wqkvl,
                                   p_wqh, p_wql, p_wkh, p_wkl,
                                   p_gram, p_ssq, p_ssk);                        // 0

    // 1) xq = w_qkv @ x  (M=384, K=128), x fp32 converted during staging
    tc_gemm_f16_bf32<<<dim3(3, 128, BATCH), 256, STG_BYTES>>>(                   // 1
        p_wqkvh, p_wqkvl, 128, (size_t)0,
        x, (size_t)CB * HWSZ, (size_t)CB * HWSZ,
        p_xq16, (size_t)C3 * HWSZ);

    // 2) depthwise conv -> D fp16
    dwconv_kernel<<<dim3(2, 8, BATCH * C3), 256>>>(p_xq16, w_dw3, w_dw5, w_dw7, p_D16);  // 2

    // 3) fused q/k projections + gram + sumsq     [profiled launch]
    qk_gram<<<dim3(128, BATCH), 256, QKG_BYTES>>>(                               // 3
        p_wqh, p_wql, p_wkh, p_wkl, p_D16, p_gram, p_ssq, p_ssk);

    attn_finalize<<<BATCH * HEADS, 32>>>(p_gram, p_ssq, p_ssk, temp, p_attn);

    // 4) M_b = w_out @ blockdiag(attn) @ w_v -> fp16 split
    t1_kernel<<<BATCH * CB, 384>>>(p_attn, w_v, p_T1);
    m_kernel<<<BATCH * CB, 384>>>(w_out, p_T1, p_M);
    cvt_split_h<<<384, 256>>>(p_M, p_Mh, p_Ml, BATCH * CB * C3 / 4);

    // 5) out = M_b @ D(v-part)  (M=128, K=384)
    tc_gemm_f32<<<dim3(1, 128, BATCH), 256, STG_BYTES>>>(
        p_Mh, p_Ml, 384, (size_t)CB * C3,
        p_D16 + (size_t)2 * CB * HWSZ, (size_t)3 * C3 * HWSZ, (size_t)C3 * HWSZ,
        out, (size_t)CB * HWSZ);
}